// round 11
// baseline (speedup 1.0000x reference)
#include <cuda_runtime.h>
#include <math.h>

#define BATCH 4
#define RAYS  4096
#define NR    (BATCH * RAYS)
#define NCH   32
#define HRES  256
#define HPAD  258
#define PLSZ  (HPAD * HPAD * NCH)
#define SC    48
#define NI    48
#define NALL  96
#define STEPF ((3.3f - 2.25f) / 47.0f)

// Bordered transposed planes: (B,3,258,258,C); 1-px border stays zero.
__device__ float g_planesT[(size_t)BATCH * 3 * PLSZ];
__device__ float g_sigma[(size_t)NR * NALL];
__device__ float g_rgbb[(size_t)NR * NALL * NCH];
__device__ float g_zfine[(size_t)NR * NI];
// Packed decode weights: [0..511] f4 = w2p pairs, [512..527] f4 = wsig2,
// [528..543] f4 = b1 pairs, floats 2176..2207 = b2[1..32], 2208 = b2[0].
__device__ float4 g_wpack[560];
// Precomputed bg layer-1 partial: bb1[u] + sum_i zbg[b,i]*bw1[3+i][u]
__device__ float g_bgz[BATCH][64];

__device__ __forceinline__ float softplusf_fast(float x) {
    return fmaxf(x, 0.0f) + __logf(1.0f + __expf(-fabsf(x)));
}
__device__ __forceinline__ float sigmoidf_fast(float x) {
    return 1.0f / (1.0f + __expf(-x));
}
__device__ __forceinline__ float2 ffma2(float2 a, float2 b, float2 c) {
    unsigned long long ra = *reinterpret_cast<unsigned long long*>(&a);
    unsigned long long rb = *reinterpret_cast<unsigned long long*>(&b);
    unsigned long long rc = *reinterpret_cast<unsigned long long*>(&c);
    unsigned long long rd;
    asm("fma.rn.f32x2 %0, %1, %2, %3;" : "=l"(rd) : "l"(ra), "l"(rb), "l"(rc));
    return *reinterpret_cast<float2*>(&rd);
}

// ---------------------------------------------------------------------------
// Pack decode weights + precompute bg z-partial. 256 threads.
// ---------------------------------------------------------------------------
__global__ void pack_weights_kernel(const float* __restrict__ b1,
                                    const float* __restrict__ w2,
                                    const float* __restrict__ b2,
                                    const float* __restrict__ zbg,
                                    const float* __restrict__ bw1,
                                    const float* __restrict__ bb1) {
    const int tid = threadIdx.x;
    float2* wp2 = (float2*)g_wpack;
    float*  wpf = (float*)g_wpack;
    for (int i = tid; i < 1024; i += 256) {
        const int k = i >> 5, ch = i & 31;
        wp2[i] = make_float2(w2[(2 * k) * 33 + 1 + ch], w2[(2 * k + 1) * 33 + 1 + ch]);
    }
    if (tid < 32) {
        wp2[1024 + tid] = make_float2(w2[(2 * tid) * 33], w2[(2 * tid + 1) * 33]);
        wp2[1056 + tid] = ((const float2*)b1)[tid];
        wpf[2176 + tid] = b2[1 + tid];
    }
    if (tid == 0) wpf[2208] = b2[0];
    // bg z-partial: tid = b*64 + u
    {
        const int b = tid >> 6, u = tid & 63;
        float acc = bb1[u];
        #pragma unroll 4
        for (int i = 0; i < 64; i++)
            acc = fmaf(zbg[b * 64 + i], bw1[(3 + i) * 64 + u], acc);
        g_bgz[b][u] = acc;
    }
}

// ---------------------------------------------------------------------------
// Transpose (B,3,C,256,256) -> bordered (B,3,258,258,C)
// ---------------------------------------------------------------------------
__global__ void transpose_planes_kernel(const float* __restrict__ planes) {
    __shared__ float tile[32][33];
    const int bp  = blockIdx.y;
    const int hw0 = blockIdx.x * 32;
    const float* src = planes + (size_t)bp * NCH * HRES * HRES;
    #pragma unroll
    for (int c = threadIdx.y; c < 32; c += 8)
        tile[c][threadIdx.x] = src[(size_t)c * (HRES * HRES) + hw0 + threadIdx.x];
    __syncthreads();
    float* dst = g_planesT + (size_t)bp * PLSZ;
    #pragma unroll
    for (int r = threadIdx.y; r < 32; r += 8) {
        const int hw = hw0 + r;
        const int y = hw >> 8, x = hw & 255;
        dst[(size_t)((y + 1) * HPAD + (x + 1)) * NCH + threadIdx.x] = tile[threadIdx.x][r];
    }
}

// ---------------------------------------------------------------------------
// Decode: 6 warps/block, each warp does 2 chunks of 8 samples.
// ---------------------------------------------------------------------------
__global__ __launch_bounds__(192, 4) void decode_kernel(
    const float* __restrict__ ro, const float* __restrict__ rd,
    const float* __restrict__ w1, const int fine)
{
    __shared__ __align__(16) float2 sw1p[32 * 32];
    __shared__ __align__(16) float2 sw2p[32 * 32];
    __shared__ __align__(16) float2 wsig2[32];
    __shared__ __align__(16) float2 sb1p[32];
    __shared__ float  sb2r[32];
    __shared__ float  sb2sig;
    __shared__ __align__(16) float sstage[6][1152];

    const int tid  = threadIdx.x;
    const int warp = tid >> 5;
    const int lane = tid & 31;

    {   // stage weights: contiguous float4 copies
        const float4* w1v4 = (const float4*)w1;
        float4* d1 = (float4*)sw1p;
        for (int i = tid; i < 512; i += 192) d1[i] = w1v4[i];
        float4* d2 = (float4*)sw2p;
        for (int i = tid; i < 512; i += 192) d2[i] = g_wpack[i];
        if (tid < 16) {
            ((float4*)wsig2)[tid] = g_wpack[512 + tid];
            ((float4*)sb1p)[tid]  = g_wpack[528 + tid];
        }
        const float* wpf = (const float*)g_wpack;
        if (tid >= 32 && tid < 64) sb2r[tid - 32] = wpf[2176 + tid - 32];
        if (tid == 64) sb2sig = wpf[2208];
    }
    __syncthreads();

    float* stg = sstage[warp];
    const int soff = fine ? SC : 0;

    #pragma unroll 1
    for (int half = 0; half < 2; half++) {
        const int gw    = blockIdx.x * 12 + warp * 2 + half;
        const int ray   = gw / 6;
        const int sbase = (gw % 6) * 8;
        const int b     = ray >> 12;

        const float ox = __ldg(ro + ray * 3 + 0);
        const float oy = __ldg(ro + ray * 3 + 1);
        const float oz = __ldg(ro + ray * 3 + 2);
        const float dx = __ldg(rd + ray * 3 + 0);
        const float dy = __ldg(rd + ray * 3 + 1);
        const float dz = __ldg(rd + ray * 3 + 2);

        const float axc = 256.0f * dx, bxc = fmaf(256.0f, ox, 127.5f);
        const float ayc = 256.0f * dy, byc = fmaf(256.0f, oy, 127.5f);
        const float azc = 256.0f * dz, bzc = fmaf(256.0f, oz, 127.5f);

        const float* pb = g_planesT + (size_t)(b * 3) * PLSZ + (HPAD + 1) * NCH + lane;

        // --- gather 8 samples (lane = channel; zero-border taps) ---
        float ff[8];
        #pragma unroll
        for (int s = 0; s < 8; s++) {
            float t;
            if (fine) t = __ldg(&g_zfine[(size_t)ray * NI + sbase + s]);
            else      t = 2.25f + ((float)(sbase + s) + 0.5f) * STEPF;
            const float X = fmaf(t, axc, bxc);
            const float Y = fmaf(t, ayc, byc);
            const float Z = fmaf(t, azc, bzc);
            float feat = 0.0f;
            #pragma unroll
            for (int p = 0; p < 3; p++) {
                const float x = (p == 2) ? Z : X;
                const float y = (p == 0) ? Y : ((p == 1) ? Z : X);
                const float x0f = floorf(x), y0f = floorf(y);
                const float wx = x - x0f, wy = y - y0f;
                const int x0 = (int)x0f, y0 = (int)y0f;
                const int x0c = min(max(x0,     -1), 256);
                const int x1c = min(max(x0 + 1, -1), 256);
                const int y0c = min(max(y0,     -1), 256);
                const int y1c = min(max(y0 + 1, -1), 256);
                const float* base = pb + (size_t)p * PLSZ;
                const int r0 = y0c * HPAD, r1 = y1c * HPAD;
                const float v00 = __ldg(base + (r0 + x0c) * NCH);
                const float v10 = __ldg(base + (r0 + x1c) * NCH);
                const float v01 = __ldg(base + (r1 + x0c) * NCH);
                const float v11 = __ldg(base + (r1 + x1c) * NCH);
                const float iwx = 1.0f - wx, iwy = 1.0f - wy;
                feat += (v00 * iwx + v10 * wx) * iwy + (v01 * iwx + v11 * wx) * wy;
            }
            ff[s] = feat * (1.0f / 3.0f);
        }
        *(float4*)(stg + lane * 12)     = make_float4(ff[0], ff[1], ff[2], ff[3]);
        *(float4*)(stg + lane * 12 + 4) = make_float4(ff[4], ff[5], ff[6], ff[7]);
        __syncwarp();

        // --- hidden layer ---
        float2 acc[8];
        {
            const float2 bp = sb1p[lane];
            #pragma unroll
            for (int s = 0; s < 8; s++) acc[s] = bp;
        }
        #pragma unroll 4
        for (int c = 0; c < 32; c++) {
            const float4 f03 = *(const float4*)(stg + c * 12);
            const float4 f47 = *(const float4*)(stg + c * 12 + 4);
            const float2 w = sw1p[c * 32 + lane];
            acc[0] = ffma2(make_float2(f03.x, f03.x), w, acc[0]);
            acc[1] = ffma2(make_float2(f03.y, f03.y), w, acc[1]);
            acc[2] = ffma2(make_float2(f03.z, f03.z), w, acc[2]);
            acc[3] = ffma2(make_float2(f03.w, f03.w), w, acc[3]);
            acc[4] = ffma2(make_float2(f47.x, f47.x), w, acc[4]);
            acc[5] = ffma2(make_float2(f47.y, f47.y), w, acc[5]);
            acc[6] = ffma2(make_float2(f47.z, f47.z), w, acc[6]);
            acc[7] = ffma2(make_float2(f47.w, f47.w), w, acc[7]);
        }
        float h0[8], h1[8];
        #pragma unroll
        for (int s = 0; s < 8; s++) {
            h0[s] = softplusf_fast(acc[s].x);
            h1[s] = softplusf_fast(acc[s].y);
        }

        // --- sigma partials + butterfly ---
        float p[8];
        {
            const float2 ws = wsig2[lane];
            #pragma unroll
            for (int s = 0; s < 8; s++) p[s] = fmaf(h0[s], ws.x, h1[s] * ws.y);
        }
        #pragma unroll
        for (int off = 16; off; off >>= 1) {
            #pragma unroll
            for (int s = 0; s < 8; s++)
                p[s] += __shfl_xor_sync(0xffffffffu, p[s], off);
        }

        __syncwarp();
        *(float4*)(stg + lane * 36 + 0)  = make_float4(h0[0], h1[0], h0[1], h1[1]);
        *(float4*)(stg + lane * 36 + 4)  = make_float4(h0[2], h1[2], h0[3], h1[3]);
        *(float4*)(stg + lane * 36 + 8)  = make_float4(h0[4], h1[4], h0[5], h1[5]);
        *(float4*)(stg + lane * 36 + 12) = make_float4(h0[6], h1[6], h0[7], h1[7]);
        __syncwarp();

        // --- output layer ---
        float2 o2[8];
        #pragma unroll
        for (int s = 0; s < 8; s++) o2[s] = make_float2(0.0f, 0.0f);
        #pragma unroll 4
        for (int k = 0; k < 32; k++) {
            const float2 w = sw2p[k * 32 + lane];
            const float4 q0 = *(const float4*)(stg + k * 36 + 0);
            const float4 q1 = *(const float4*)(stg + k * 36 + 4);
            const float4 q2 = *(const float4*)(stg + k * 36 + 8);
            const float4 q3 = *(const float4*)(stg + k * 36 + 12);
            o2[0] = ffma2(make_float2(q0.x, q0.y), w, o2[0]);
            o2[1] = ffma2(make_float2(q0.z, q0.w), w, o2[1]);
            o2[2] = ffma2(make_float2(q1.x, q1.y), w, o2[2]);
            o2[3] = ffma2(make_float2(q1.z, q1.w), w, o2[3]);
            o2[4] = ffma2(make_float2(q2.x, q2.y), w, o2[4]);
            o2[5] = ffma2(make_float2(q2.z, q2.w), w, o2[5]);
            o2[6] = ffma2(make_float2(q3.x, q3.y), w, o2[6]);
            o2[7] = ffma2(make_float2(q3.z, q3.w), w, o2[7]);
        }

        const float bb = sb2r[lane];
        float* grow = g_rgbb + ((size_t)ray * NALL + soff + sbase) * NCH + lane;
        #pragma unroll
        for (int s = 0; s < 8; s++)
            grow[s * NCH] = sigmoidf_fast(o2[s].x + o2[s].y + bb) * 1.002f - 0.001f;

        float myp = p[0];
        if (lane == 1) myp = p[1];
        if (lane == 2) myp = p[2];
        if (lane == 3) myp = p[3];
        if (lane == 4) myp = p[4];
        if (lane == 5) myp = p[5];
        if (lane == 6) myp = p[6];
        if (lane == 7) myp = p[7];
        if (lane < 8)
            g_sigma[(size_t)ray * NALL + soff + sbase + lane] = myp + sb2sig;
        __syncwarp();
    }
}

// ---------------------------------------------------------------------------
// March: warp-parallel predicated scans.
// ---------------------------------------------------------------------------
__global__ __launch_bounds__(128) void march_kernel() {
    __shared__ float salpha[4][47];
    __shared__ float swcl[4][47];
    __shared__ float swk[4][45];
    __shared__ float scdf[4][46];

    const int warp = threadIdx.x >> 5;
    const int lane = threadIdx.x & 31;
    const int ray  = blockIdx.x * 4 + warp;

    const float* sg = g_sigma + (size_t)ray * NALL;
    for (int i = lane; i < 47; i += 32) {
        const float dens = softplusf_fast(0.5f * (__ldg(sg + i) + __ldg(sg + i + 1)) - 1.0f);
        salpha[warp][i] = 1.0f - __expf(-dens * STEPF);
    }
    __syncwarp();

    {
        float Ta = 1.0f, Tb = 1.0f;
        #pragma unroll 4
        for (int j = 0; j < 46; j++) {
            const float fj = 1.0f - salpha[warp][j] + 1e-10f;
            if (j < lane)      Ta *= fj;
            if (j < lane + 32) Tb *= fj;
        }
        swcl[warp][lane] = salpha[warp][lane] * Ta;
        if (lane + 32 < 47)
            swcl[warp][lane + 32] = salpha[warp][lane + 32] * Tb;
    }
    __syncwarp();

    float ssum = 0.0f;
    #pragma unroll
    for (int kk = 0; kk < 2; kk++) {
        const int k = lane + kk * 32;
        if (k < 45) {
            const float a  = fmaxf(swcl[warp][k],     swcl[warp][k + 1]) + 0.01f;
            const float bb = fmaxf(swcl[warp][k + 1], swcl[warp][k + 2]) + 0.01f;
            const float v  = 0.5f * (a + bb) + 0.01f + 1e-5f;
            swk[warp][k] = v;
            ssum += v;
        }
    }
    #pragma unroll
    for (int off = 16; off; off >>= 1)
        ssum += __shfl_xor_sync(0xffffffffu, ssum, off);
    const float inv = 1.0f / ssum;
    __syncwarp();

    {
        float ca = 0.0f, cb = 0.0f;
        #pragma unroll 4
        for (int j = 0; j < 45; j++) {
            const float vj = swk[warp][j];
            if (j <= lane)      ca += vj;
            if (j <= lane + 32) cb += vj;
        }
        if (lane == 0) scdf[warp][0] = 0.0f;
        scdf[warp][lane + 1] = ca * inv;
        if (lane + 33 <= 45) scdf[warp][lane + 33] = cb * inv;
    }
    __syncwarp();

    for (int i = lane; i < NI; i += 32) {
        const float u = ((float)i + 0.5f) * (1.0f / 48.0f);
        int idx = 0;
        while (idx < 46 && scdf[warp][idx] <= u) idx++;
        int below = idx - 1; if (below < 0) below = 0; if (below > 45) below = 45;
        int above = idx;     if (above > 45) above = 45;
        const float cb = scdf[warp][below], ca = scdf[warp][above];
        float den = ca - cb; if (den < 1e-5f) den = 1.0f;
        const float bbv = 2.25f + ((float)below + 1.0f) * STEPF;
        const float bav = 2.25f + ((float)above + 1.0f) * STEPF;
        g_zfine[(size_t)ray * NI + i] = fmaf((u - cb) / den, bav - bbv, bbv);
    }
}

// ---------------------------------------------------------------------------
// Final: merge + parallel-scan march + cheap bg MLP + composite. 1 warp/ray.
// ---------------------------------------------------------------------------
__global__ __launch_bounds__(128) void final_kernel(
    const float* __restrict__ rd,
    const float* __restrict__ bw1, const float* __restrict__ bw2,
    const float* __restrict__ bb2, float* __restrict__ out)
{
    __shared__ float zall[4][NALL];
    __shared__ float sig[4][NALL];
    __shared__ unsigned char perm[4][NALL];
    __shared__ float alpha_s[4][NALL - 1];
    __shared__ float wall[4][NALL - 1];
    __shared__ float bgh[4][64];
    __shared__ __align__(16) float sbw2[64 * 32];

    const int tid  = threadIdx.x;
    const int warp = tid >> 5;
    const int lane = tid & 31;
    const int ray  = blockIdx.x * 4 + warp;
    const int b    = ray >> 12;

    // stage bw2 (8KB) once per block
    {
        const float4* src = (const float4*)bw2;
        float4* dst = (float4*)sbw2;
        #pragma unroll
        for (int i = tid; i < 512; i += 128) dst[i] = src[i];
    }

    const float dx = __ldg(rd + ray * 3 + 0);
    const float dy = __ldg(rd + ray * 3 + 1);
    const float dz = __ldg(rd + ray * 3 + 2);

    for (int i = lane; i < NALL; i += 32) {
        sig[warp][i] = __ldg(&g_sigma[(size_t)ray * NALL + i]);
        zall[warp][i] = (i < SC) ? (2.25f + ((float)i + 0.5f) * STEPF)
                                 : __ldg(&g_zfine[(size_t)ray * NI + i - SC]);
    }

    // --- bg layer 1: z-part precomputed (g_bgz), only 3 direction FMAs ---
    {
        float a0 = g_bgz[b][lane]      ;
        float a1 = g_bgz[b][lane + 32];
        a0 = fmaf(dx, __ldg(bw1 + 0 * 64 + lane), a0);
        a1 = fmaf(dx, __ldg(bw1 + 0 * 64 + 32 + lane), a1);
        a0 = fmaf(dy, __ldg(bw1 + 1 * 64 + lane), a0);
        a1 = fmaf(dy, __ldg(bw1 + 1 * 64 + 32 + lane), a1);
        a0 = fmaf(dz, __ldg(bw1 + 2 * 64 + lane), a0);
        a1 = fmaf(dz, __ldg(bw1 + 2 * 64 + 32 + lane), a1);
        bgh[warp][lane]      = softplusf_fast(a0);
        bgh[warp][lane + 32] = softplusf_fast(a1);
    }
    __syncthreads();   // bw2 staged + bgh ready

    float bgc_r = __ldg(bb2 + lane);
    #pragma unroll 8
    for (int h = 0; h < 64; h++)
        bgc_r = fmaf(bgh[warp][h], sbw2[h * 32 + lane], bgc_r);
    bgc_r = sigmoidf_fast(bgc_r);
    __syncwarp();

    // --- stable merge by rank-counting ---
    for (int i = lane; i < SC; i += 32) {
        const float zv = zall[warp][i];
        int c = 0;
        #pragma unroll 8
        for (int k = 0; k < NI; k++) c += (zall[warp][SC + k] < zv) ? 1 : 0;
        perm[warp][i + c] = (unsigned char)i;
    }
    for (int j = lane; j < NI; j += 32) {
        const float zv = zall[warp][SC + j];
        int c = 0;
        #pragma unroll 8
        for (int k = 0; k < SC; k++) c += (zall[warp][k] <= zv) ? 1 : 0;
        perm[warp][j + c] = (unsigned char)(SC + j);
    }
    __syncwarp();

    for (int k = lane; k < NALL - 1; k += 32) {
        const float delta = zall[warp][perm[warp][k + 1]] - zall[warp][perm[warp][k]];
        const float dens  = softplusf_fast(0.5f * (sig[warp][perm[warp][k]] +
                                                   sig[warp][perm[warp][k + 1]]) - 1.0f);
        alpha_s[warp][k] = 1.0f - __expf(-dens * delta);
    }
    __syncwarp();

    // --- transmittance: predicated product scan over 95 factors ---
    float T0 = 1.0f, T1 = 1.0f, T2 = 1.0f, Tall = 1.0f;
    #pragma unroll 4
    for (int j = 0; j < NALL - 1; j++) {
        const float fj = 1.0f - alpha_s[warp][j] + 1e-10f;
        if (j < lane)      T0 *= fj;
        if (j < lane + 32) T1 *= fj;
        if (j < lane + 64) T2 *= fj;
        Tall *= fj;
    }
    float wt = 0.0f, dacc = 0.0f;
    {
        const int k = lane;
        const float w = alpha_s[warp][k] * T0;
        wall[warp][k] = w;
        wt += w;
        dacc = fmaf(w, 0.5f * (zall[warp][perm[warp][k]] + zall[warp][perm[warp][k + 1]]), dacc);
    }
    {
        const int k = lane + 32;
        const float w = alpha_s[warp][k] * T1;
        wall[warp][k] = w;
        wt += w;
        dacc = fmaf(w, 0.5f * (zall[warp][perm[warp][k]] + zall[warp][perm[warp][k + 1]]), dacc);
    }
    if (lane + 64 < NALL - 1) {
        const int k = lane + 64;
        const float w = alpha_s[warp][k] * T2;
        wall[warp][k] = w;
        wt += w;
        dacc = fmaf(w, 0.5f * (zall[warp][perm[warp][k]] + zall[warp][perm[warp][k + 1]]), dacc);
    }
    #pragma unroll
    for (int off = 16; off; off >>= 1) {
        wt   += __shfl_xor_sync(0xffffffffu, wt, off);
        dacc += __shfl_xor_sync(0xffffffffu, dacc, off);
    }
    __syncwarp();

    // --- composite (lane = channel) ---
    const size_t rbase = (size_t)ray * NALL * NCH + lane;
    float rprev = __ldg(&g_rgbb[rbase + (size_t)perm[warp][0] * NCH]);
    float acc = 0.0f;
    #pragma unroll 5
    for (int k = 0; k < NALL - 1; k++) {
        const float rnext = __ldg(&g_rgbb[rbase + (size_t)perm[warp][k + 1] * NCH]);
        acc = fmaf(wall[warp][k], 0.5f * (rprev + rnext), acc);
        rprev = rnext;
    }
    acc = fmaf(Tall, bgc_r, acc);

    float* out_rgb   = out;
    float* out_depth = out + (size_t)NR * 32;
    float* out_wsum  = out + (size_t)NR * 33;

    out_rgb[(size_t)ray * 32 + lane] = acc * 2.0f - 1.0f;
    if (lane == 0) {
        float dv = dacc / wt;
        if (dv != dv) dv = INFINITY;
        const float ZMIN = 2.25f + 0.5f  * STEPF;
        const float ZMAX = 2.25f + 47.5f * STEPF;
        dv = fminf(fmaxf(dv, ZMIN), ZMAX);
        out_depth[ray] = dv;
        out_wsum[ray]  = wt;
    }
}

// ---------------------------------------------------------------------------
extern "C" void kernel_launch(void* const* d_in, const int* in_sizes, int n_in,
                              void* d_out, int out_size) {
    const float* planes = (const float*)d_in[0];
    const float* ro     = (const float*)d_in[1];
    const float* rd     = (const float*)d_in[2];
    const float* zbg    = (const float*)d_in[3];
    const float* w1     = (const float*)d_in[4];
    const float* b1     = (const float*)d_in[5];
    const float* w2     = (const float*)d_in[6];
    const float* b2     = (const float*)d_in[7];
    const float* bw1    = (const float*)d_in[8];
    const float* bb1    = (const float*)d_in[9];
    const float* bw2    = (const float*)d_in[10];
    const float* bb2    = (const float*)d_in[11];
    float* out = (float*)d_out;

    pack_weights_kernel<<<1, 256>>>(b1, w2, b2, zbg, bw1, bb1);
    dim3 tgrid(HRES * HRES / 32, BATCH * 3);
    transpose_planes_kernel<<<tgrid, dim3(32, 8)>>>(planes);

    const int decode_blocks = NR * 6 / 12;   // 12 chunks per block
    decode_kernel<<<decode_blocks, 192>>>(ro, rd, w1, 0);
    march_kernel<<<NR / 4, 128>>>();
    decode_kernel<<<decode_blocks, 192>>>(ro, rd, w1, 1);
    final_kernel<<<NR / 4, 128>>>(rd, bw1, bw2, bb2, out);
}

// round 12
// speedup vs baseline: 1.5564x; 1.5564x over previous
#include <cuda_runtime.h>
#include <math.h>

#define BATCH 4
#define RAYS  4096
#define NR    (BATCH * RAYS)
#define NCH   32
#define HRES  256
#define HPAD  258
#define PLSZ  (HPAD * HPAD * NCH)
#define SC    48
#define NI    48
#define NALL  96
#define STEPF ((3.3f - 2.25f) / 47.0f)

// Bordered transposed planes: (B,3,258,258,C); 1-px border stays zero.
__device__ float g_planesT[(size_t)BATCH * 3 * PLSZ];
__device__ float g_sigma[(size_t)NR * NALL];
__device__ float g_rgbb[(size_t)NR * NALL * NCH];
__device__ float g_zfine[(size_t)NR * NI];
// Packed decode weights: [0..511] f4 = w2p pairs, [512..527] f4 = wsig2,
// [528..543] f4 = b1 pairs, floats 2176..2207 = b2[1..32], 2208 = b2[0].
__device__ float4 g_wpack[560];
// Precomputed bg layer-1 partial: bb1[u] + sum_i zbg[b,i]*bw1[3+i][u]
__device__ float g_bgz[BATCH][64];

__device__ __forceinline__ float softplusf_fast(float x) {
    return fmaxf(x, 0.0f) + __logf(1.0f + __expf(-fabsf(x)));
}
__device__ __forceinline__ float sigmoidf_fast(float x) {
    return 1.0f / (1.0f + __expf(-x));
}
__device__ __forceinline__ float2 ffma2(float2 a, float2 b, float2 c) {
    unsigned long long ra = *reinterpret_cast<unsigned long long*>(&a);
    unsigned long long rb = *reinterpret_cast<unsigned long long*>(&b);
    unsigned long long rc = *reinterpret_cast<unsigned long long*>(&c);
    unsigned long long rd;
    asm("fma.rn.f32x2 %0, %1, %2, %3;" : "=l"(rd) : "l"(ra), "l"(rb), "l"(rc));
    return *reinterpret_cast<float2*>(&rd);
}

// ---------------------------------------------------------------------------
// Pack decode weights + precompute bg z-partial. 256 threads.
// ---------------------------------------------------------------------------
__global__ void pack_weights_kernel(const float* __restrict__ b1,
                                    const float* __restrict__ w2,
                                    const float* __restrict__ b2,
                                    const float* __restrict__ zbg,
                                    const float* __restrict__ bw1,
                                    const float* __restrict__ bb1) {
    const int tid = threadIdx.x;
    float2* wp2 = (float2*)g_wpack;
    float*  wpf = (float*)g_wpack;
    for (int i = tid; i < 1024; i += 256) {
        const int k = i >> 5, ch = i & 31;
        wp2[i] = make_float2(w2[(2 * k) * 33 + 1 + ch], w2[(2 * k + 1) * 33 + 1 + ch]);
    }
    if (tid < 32) {
        wp2[1024 + tid] = make_float2(w2[(2 * tid) * 33], w2[(2 * tid + 1) * 33]);
        wp2[1056 + tid] = ((const float2*)b1)[tid];
        wpf[2176 + tid] = b2[1 + tid];
    }
    if (tid == 0) wpf[2208] = b2[0];
    // bg z-partial: tid = b*64 + u
    {
        const int b = tid >> 6, u = tid & 63;
        float acc = bb1[u];
        #pragma unroll 4
        for (int i = 0; i < 64; i++)
            acc = fmaf(zbg[b * 64 + i], bw1[(3 + i) * 64 + u], acc);
        g_bgz[b][u] = acc;
    }
}

// ---------------------------------------------------------------------------
// Transpose (B,3,C,256,256) -> bordered (B,3,258,258,C)
// ---------------------------------------------------------------------------
__global__ void transpose_planes_kernel(const float* __restrict__ planes) {
    __shared__ float tile[32][33];
    const int bp  = blockIdx.y;
    const int hw0 = blockIdx.x * 32;
    const float* src = planes + (size_t)bp * NCH * HRES * HRES;
    #pragma unroll
    for (int c = threadIdx.y; c < 32; c += 8)
        tile[c][threadIdx.x] = src[(size_t)c * (HRES * HRES) + hw0 + threadIdx.x];
    __syncthreads();
    float* dst = g_planesT + (size_t)bp * PLSZ;
    #pragma unroll
    for (int r = threadIdx.y; r < 32; r += 8) {
        const int hw = hw0 + r;
        const int y = hw >> 8, x = hw & 255;
        dst[(size_t)((y + 1) * HPAD + (x + 1)) * NCH + threadIdx.x] = tile[threadIdx.x][r];
    }
}

// ---------------------------------------------------------------------------
// Decode: sample-parallel warp-GEMM. 1 warp = 8 samples of one ray.
// (Exact R10 configuration — 128 threads, launch_bounds(128,6).)
// ---------------------------------------------------------------------------
__global__ __launch_bounds__(128, 6) void decode_kernel(
    const float* __restrict__ ro, const float* __restrict__ rd,
    const float* __restrict__ w1, const int fine)
{
    __shared__ __align__(16) float2 sw1p[32 * 32];
    __shared__ __align__(16) float2 sw2p[32 * 32];
    __shared__ __align__(16) float2 wsig2[32];
    __shared__ __align__(16) float2 sb1p[32];
    __shared__ float  sb2r[32];
    __shared__ float  sb2sig;
    __shared__ __align__(16) float sstage[4][1152];

    const int tid  = threadIdx.x;
    const int warp = tid >> 5;
    const int lane = tid & 31;

    {   // stage weights: contiguous float4 copies
        const float4* w1v4 = (const float4*)w1;
        float4* d1 = (float4*)sw1p;
        #pragma unroll
        for (int i = tid; i < 512; i += 128) d1[i] = w1v4[i];
        float4* d2 = (float4*)sw2p;
        #pragma unroll
        for (int i = tid; i < 512; i += 128) d2[i] = g_wpack[i];
        if (tid < 16) {
            ((float4*)wsig2)[tid] = g_wpack[512 + tid];
            ((float4*)sb1p)[tid]  = g_wpack[528 + tid];
        }
        const float* wpf = (const float*)g_wpack;
        if (tid < 32) sb2r[tid] = wpf[2176 + tid];
        if (tid == 0) sb2sig = wpf[2208];
    }
    __syncthreads();

    const int gw    = blockIdx.x * 4 + warp;
    const int ray   = gw / 6;
    const int sbase = (gw % 6) * 8;
    const int b     = ray >> 12;
    const int soff  = fine ? SC : 0;

    const float ox = __ldg(ro + ray * 3 + 0);
    const float oy = __ldg(ro + ray * 3 + 1);
    const float oz = __ldg(ro + ray * 3 + 2);
    const float dx = __ldg(rd + ray * 3 + 0);
    const float dy = __ldg(rd + ray * 3 + 1);
    const float dz = __ldg(rd + ray * 3 + 2);

    // premultiplied pixel-space ray constants: x_px = t*a + b
    const float axc = 256.0f * dx, bxc = fmaf(256.0f, ox, 127.5f);
    const float ayc = 256.0f * dy, byc = fmaf(256.0f, oy, 127.5f);
    const float azc = 256.0f * dz, bzc = fmaf(256.0f, oz, 127.5f);

    const float* pb = g_planesT + (size_t)(b * 3) * PLSZ + (HPAD + 1) * NCH + lane;
    float* stg = sstage[warp];

    // --- gather 8 samples (lane = channel; zero-border taps) ---
    float ff[8];
    #pragma unroll
    for (int s = 0; s < 8; s++) {
        float t;
        if (fine) t = __ldg(&g_zfine[(size_t)ray * NI + sbase + s]);
        else      t = 2.25f + ((float)(sbase + s) + 0.5f) * STEPF;
        const float X = fmaf(t, axc, bxc);
        const float Y = fmaf(t, ayc, byc);
        const float Z = fmaf(t, azc, bzc);
        float feat = 0.0f;
        #pragma unroll
        for (int p = 0; p < 3; p++) {
            const float x = (p == 2) ? Z : X;
            const float y = (p == 0) ? Y : ((p == 1) ? Z : X);
            const float x0f = floorf(x), y0f = floorf(y);
            const float wx = x - x0f, wy = y - y0f;
            const int x0 = (int)x0f, y0 = (int)y0f;
            const int x0c = min(max(x0,     -1), 256);
            const int x1c = min(max(x0 + 1, -1), 256);
            const int y0c = min(max(y0,     -1), 256);
            const int y1c = min(max(y0 + 1, -1), 256);
            const float* base = pb + (size_t)p * PLSZ;
            const int r0 = y0c * HPAD, r1 = y1c * HPAD;
            const float v00 = __ldg(base + (r0 + x0c) * NCH);
            const float v10 = __ldg(base + (r0 + x1c) * NCH);
            const float v01 = __ldg(base + (r1 + x0c) * NCH);
            const float v11 = __ldg(base + (r1 + x1c) * NCH);
            const float iwx = 1.0f - wx, iwy = 1.0f - wy;
            feat += (v00 * iwx + v10 * wx) * iwy + (v01 * iwx + v11 * wx) * wy;
        }
        ff[s] = feat * (1.0f / 3.0f);
    }
    *(float4*)(stg + lane * 12)     = make_float4(ff[0], ff[1], ff[2], ff[3]);
    *(float4*)(stg + lane * 12 + 4) = make_float4(ff[4], ff[5], ff[6], ff[7]);
    __syncwarp();

    // --- hidden layer ---
    float2 acc[8];
    {
        const float2 bp = sb1p[lane];
        #pragma unroll
        for (int s = 0; s < 8; s++) acc[s] = bp;
    }
    #pragma unroll 4
    for (int c = 0; c < 32; c++) {
        const float4 f03 = *(const float4*)(stg + c * 12);
        const float4 f47 = *(const float4*)(stg + c * 12 + 4);
        const float2 w = sw1p[c * 32 + lane];
        acc[0] = ffma2(make_float2(f03.x, f03.x), w, acc[0]);
        acc[1] = ffma2(make_float2(f03.y, f03.y), w, acc[1]);
        acc[2] = ffma2(make_float2(f03.z, f03.z), w, acc[2]);
        acc[3] = ffma2(make_float2(f03.w, f03.w), w, acc[3]);
        acc[4] = ffma2(make_float2(f47.x, f47.x), w, acc[4]);
        acc[5] = ffma2(make_float2(f47.y, f47.y), w, acc[5]);
        acc[6] = ffma2(make_float2(f47.z, f47.z), w, acc[6]);
        acc[7] = ffma2(make_float2(f47.w, f47.w), w, acc[7]);
    }
    float h0[8], h1[8];
    #pragma unroll
    for (int s = 0; s < 8; s++) {
        h0[s] = softplusf_fast(acc[s].x);
        h1[s] = softplusf_fast(acc[s].y);
    }

    // --- sigma partials + butterfly ---
    float p[8];
    {
        const float2 ws = wsig2[lane];
        #pragma unroll
        for (int s = 0; s < 8; s++) p[s] = fmaf(h0[s], ws.x, h1[s] * ws.y);
    }
    #pragma unroll
    for (int off = 16; off; off >>= 1) {
        #pragma unroll
        for (int s = 0; s < 8; s++)
            p[s] += __shfl_xor_sync(0xffffffffu, p[s], off);
    }

    __syncwarp();
    *(float4*)(stg + lane * 36 + 0)  = make_float4(h0[0], h1[0], h0[1], h1[1]);
    *(float4*)(stg + lane * 36 + 4)  = make_float4(h0[2], h1[2], h0[3], h1[3]);
    *(float4*)(stg + lane * 36 + 8)  = make_float4(h0[4], h1[4], h0[5], h1[5]);
    *(float4*)(stg + lane * 36 + 12) = make_float4(h0[6], h1[6], h0[7], h1[7]);
    __syncwarp();

    // --- output layer ---
    float2 o2[8];
    #pragma unroll
    for (int s = 0; s < 8; s++) o2[s] = make_float2(0.0f, 0.0f);
    #pragma unroll 4
    for (int k = 0; k < 32; k++) {
        const float2 w = sw2p[k * 32 + lane];
        const float4 q0 = *(const float4*)(stg + k * 36 + 0);
        const float4 q1 = *(const float4*)(stg + k * 36 + 4);
        const float4 q2 = *(const float4*)(stg + k * 36 + 8);
        const float4 q3 = *(const float4*)(stg + k * 36 + 12);
        o2[0] = ffma2(make_float2(q0.x, q0.y), w, o2[0]);
        o2[1] = ffma2(make_float2(q0.z, q0.w), w, o2[1]);
        o2[2] = ffma2(make_float2(q1.x, q1.y), w, o2[2]);
        o2[3] = ffma2(make_float2(q1.z, q1.w), w, o2[3]);
        o2[4] = ffma2(make_float2(q2.x, q2.y), w, o2[4]);
        o2[5] = ffma2(make_float2(q2.z, q2.w), w, o2[5]);
        o2[6] = ffma2(make_float2(q3.x, q3.y), w, o2[6]);
        o2[7] = ffma2(make_float2(q3.z, q3.w), w, o2[7]);
    }

    const float bb = sb2r[lane];
    float* grow = g_rgbb + ((size_t)ray * NALL + soff + sbase) * NCH + lane;
    #pragma unroll
    for (int s = 0; s < 8; s++)
        grow[s * NCH] = sigmoidf_fast(o2[s].x + o2[s].y + bb) * 1.002f - 0.001f;

    float myp = p[0];
    if (lane == 1) myp = p[1];
    if (lane == 2) myp = p[2];
    if (lane == 3) myp = p[3];
    if (lane == 4) myp = p[4];
    if (lane == 5) myp = p[5];
    if (lane == 6) myp = p[6];
    if (lane == 7) myp = p[7];
    if (lane < 8)
        g_sigma[(size_t)ray * NALL + soff + sbase + lane] = myp + sb2sig;
}

// ---------------------------------------------------------------------------
// March: warp-parallel predicated scans.
// ---------------------------------------------------------------------------
__global__ __launch_bounds__(128) void march_kernel() {
    __shared__ float salpha[4][47];
    __shared__ float swcl[4][47];
    __shared__ float swk[4][45];
    __shared__ float scdf[4][46];

    const int warp = threadIdx.x >> 5;
    const int lane = threadIdx.x & 31;
    const int ray  = blockIdx.x * 4 + warp;

    const float* sg = g_sigma + (size_t)ray * NALL;
    for (int i = lane; i < 47; i += 32) {
        const float dens = softplusf_fast(0.5f * (__ldg(sg + i) + __ldg(sg + i + 1)) - 1.0f);
        salpha[warp][i] = 1.0f - __expf(-dens * STEPF);
    }
    __syncwarp();

    {
        float Ta = 1.0f, Tb = 1.0f;
        #pragma unroll 4
        for (int j = 0; j < 46; j++) {
            const float fj = 1.0f - salpha[warp][j] + 1e-10f;
            if (j < lane)      Ta *= fj;
            if (j < lane + 32) Tb *= fj;
        }
        swcl[warp][lane] = salpha[warp][lane] * Ta;
        if (lane + 32 < 47)
            swcl[warp][lane + 32] = salpha[warp][lane + 32] * Tb;
    }
    __syncwarp();

    float ssum = 0.0f;
    #pragma unroll
    for (int kk = 0; kk < 2; kk++) {
        const int k = lane + kk * 32;
        if (k < 45) {
            const float a  = fmaxf(swcl[warp][k],     swcl[warp][k + 1]) + 0.01f;
            const float bb = fmaxf(swcl[warp][k + 1], swcl[warp][k + 2]) + 0.01f;
            const float v  = 0.5f * (a + bb) + 0.01f + 1e-5f;
            swk[warp][k] = v;
            ssum += v;
        }
    }
    #pragma unroll
    for (int off = 16; off; off >>= 1)
        ssum += __shfl_xor_sync(0xffffffffu, ssum, off);
    const float inv = 1.0f / ssum;
    __syncwarp();

    {
        float ca = 0.0f, cb = 0.0f;
        #pragma unroll 4
        for (int j = 0; j < 45; j++) {
            const float vj = swk[warp][j];
            if (j <= lane)      ca += vj;
            if (j <= lane + 32) cb += vj;
        }
        if (lane == 0) scdf[warp][0] = 0.0f;
        scdf[warp][lane + 1] = ca * inv;
        if (lane + 33 <= 45) scdf[warp][lane + 33] = cb * inv;
    }
    __syncwarp();

    for (int i = lane; i < NI; i += 32) {
        const float u = ((float)i + 0.5f) * (1.0f / 48.0f);
        int idx = 0;
        while (idx < 46 && scdf[warp][idx] <= u) idx++;
        int below = idx - 1; if (below < 0) below = 0; if (below > 45) below = 45;
        int above = idx;     if (above > 45) above = 45;
        const float cb = scdf[warp][below], ca = scdf[warp][above];
        float den = ca - cb; if (den < 1e-5f) den = 1.0f;
        const float bbv = 2.25f + ((float)below + 1.0f) * STEPF;
        const float bav = 2.25f + ((float)above + 1.0f) * STEPF;
        g_zfine[(size_t)ray * NI + i] = fmaf((u - cb) / den, bav - bbv, bbv);
    }
}

// ---------------------------------------------------------------------------
// Final: merge + parallel-scan march + cheap bg MLP + composite. 1 warp/ray.
// ---------------------------------------------------------------------------
__global__ __launch_bounds__(128) void final_kernel(
    const float* __restrict__ rd,
    const float* __restrict__ bw1, const float* __restrict__ bw2,
    const float* __restrict__ bb2, float* __restrict__ out)
{
    __shared__ float zall[4][NALL];
    __shared__ float sig[4][NALL];
    __shared__ unsigned char perm[4][NALL];
    __shared__ float alpha_s[4][NALL - 1];
    __shared__ float wall[4][NALL - 1];
    __shared__ float bgh[4][64];
    __shared__ __align__(16) float sbw2[64 * 32];

    const int tid  = threadIdx.x;
    const int warp = tid >> 5;
    const int lane = tid & 31;
    const int ray  = blockIdx.x * 4 + warp;
    const int b    = ray >> 12;

    // stage bw2 (8KB) once per block
    {
        const float4* src = (const float4*)bw2;
        float4* dst = (float4*)sbw2;
        #pragma unroll
        for (int i = tid; i < 512; i += 128) dst[i] = src[i];
    }

    const float dx = __ldg(rd + ray * 3 + 0);
    const float dy = __ldg(rd + ray * 3 + 1);
    const float dz = __ldg(rd + ray * 3 + 2);

    for (int i = lane; i < NALL; i += 32) {
        sig[warp][i] = __ldg(&g_sigma[(size_t)ray * NALL + i]);
        zall[warp][i] = (i < SC) ? (2.25f + ((float)i + 0.5f) * STEPF)
                                 : __ldg(&g_zfine[(size_t)ray * NI + i - SC]);
    }

    // --- bg layer 1: z-part precomputed (g_bgz), only 3 direction FMAs ---
    {
        float a0 = g_bgz[b][lane];
        float a1 = g_bgz[b][lane + 32];
        a0 = fmaf(dx, __ldg(bw1 + 0 * 64 + lane), a0);
        a1 = fmaf(dx, __ldg(bw1 + 0 * 64 + 32 + lane), a1);
        a0 = fmaf(dy, __ldg(bw1 + 1 * 64 + lane), a0);
        a1 = fmaf(dy, __ldg(bw1 + 1 * 64 + 32 + lane), a1);
        a0 = fmaf(dz, __ldg(bw1 + 2 * 64 + lane), a0);
        a1 = fmaf(dz, __ldg(bw1 + 2 * 64 + 32 + lane), a1);
        bgh[warp][lane]      = softplusf_fast(a0);
        bgh[warp][lane + 32] = softplusf_fast(a1);
    }
    __syncthreads();   // bw2 staged + bgh ready

    float bgc_r = __ldg(bb2 + lane);
    #pragma unroll 8
    for (int h = 0; h < 64; h++)
        bgc_r = fmaf(bgh[warp][h], sbw2[h * 32 + lane], bgc_r);
    bgc_r = sigmoidf_fast(bgc_r);
    __syncwarp();

    // --- stable merge by rank-counting ---
    for (int i = lane; i < SC; i += 32) {
        const float zv = zall[warp][i];
        int c = 0;
        #pragma unroll 8
        for (int k = 0; k < NI; k++) c += (zall[warp][SC + k] < zv) ? 1 : 0;
        perm[warp][i + c] = (unsigned char)i;
    }
    for (int j = lane; j < NI; j += 32) {
        const float zv = zall[warp][SC + j];
        int c = 0;
        #pragma unroll 8
        for (int k = 0; k < SC; k++) c += (zall[warp][k] <= zv) ? 1 : 0;
        perm[warp][j + c] = (unsigned char)(SC + j);
    }
    __syncwarp();

    for (int k = lane; k < NALL - 1; k += 32) {
        const float delta = zall[warp][perm[warp][k + 1]] - zall[warp][perm[warp][k]];
        const float dens  = softplusf_fast(0.5f * (sig[warp][perm[warp][k]] +
                                                   sig[warp][perm[warp][k + 1]]) - 1.0f);
        alpha_s[warp][k] = 1.0f - __expf(-dens * delta);
    }
    __syncwarp();

    // --- transmittance: predicated product scan over 95 factors ---
    float T0 = 1.0f, T1 = 1.0f, T2 = 1.0f, Tall = 1.0f;
    #pragma unroll 4
    for (int j = 0; j < NALL - 1; j++) {
        const float fj = 1.0f - alpha_s[warp][j] + 1e-10f;
        if (j < lane)      T0 *= fj;
        if (j < lane + 32) T1 *= fj;
        if (j < lane + 64) T2 *= fj;
        Tall *= fj;
    }
    float wt = 0.0f, dacc = 0.0f;
    {
        const int k = lane;
        const float w = alpha_s[warp][k] * T0;
        wall[warp][k] = w;
        wt += w;
        dacc = fmaf(w, 0.5f * (zall[warp][perm[warp][k]] + zall[warp][perm[warp][k + 1]]), dacc);
    }
    {
        const int k = lane + 32;
        const float w = alpha_s[warp][k] * T1;
        wall[warp][k] = w;
        wt += w;
        dacc = fmaf(w, 0.5f * (zall[warp][perm[warp][k]] + zall[warp][perm[warp][k + 1]]), dacc);
    }
    if (lane + 64 < NALL - 1) {
        const int k = lane + 64;
        const float w = alpha_s[warp][k] * T2;
        wall[warp][k] = w;
        wt += w;
        dacc = fmaf(w, 0.5f * (zall[warp][perm[warp][k]] + zall[warp][perm[warp][k + 1]]), dacc);
    }
    #pragma unroll
    for (int off = 16; off; off >>= 1) {
        wt   += __shfl_xor_sync(0xffffffffu, wt, off);
        dacc += __shfl_xor_sync(0xffffffffu, dacc, off);
    }
    __syncwarp();

    // --- composite (lane = channel) ---
    const size_t rbase = (size_t)ray * NALL * NCH + lane;
    float rprev = __ldg(&g_rgbb[rbase + (size_t)perm[warp][0] * NCH]);
    float acc = 0.0f;
    #pragma unroll 5
    for (int k = 0; k < NALL - 1; k++) {
        const float rnext = __ldg(&g_rgbb[rbase + (size_t)perm[warp][k + 1] * NCH]);
        acc = fmaf(wall[warp][k], 0.5f * (rprev + rnext), acc);
        rprev = rnext;
    }
    acc = fmaf(Tall, bgc_r, acc);

    float* out_rgb   = out;
    float* out_depth = out + (size_t)NR * 32;
    float* out_wsum  = out + (size_t)NR * 33;

    out_rgb[(size_t)ray * 32 + lane] = acc * 2.0f - 1.0f;
    if (lane == 0) {
        float dv = dacc / wt;
        if (dv != dv) dv = INFINITY;
        const float ZMIN = 2.25f + 0.5f  * STEPF;
        const float ZMAX = 2.25f + 47.5f * STEPF;
        dv = fminf(fmaxf(dv, ZMIN), ZMAX);
        out_depth[ray] = dv;
        out_wsum[ray]  = wt;
    }
}

// ---------------------------------------------------------------------------
extern "C" void kernel_launch(void* const* d_in, const int* in_sizes, int n_in,
                              void* d_out, int out_size) {
    const float* planes = (const float*)d_in[0];
    const float* ro     = (const float*)d_in[1];
    const float* rd     = (const float*)d_in[2];
    const float* zbg    = (const float*)d_in[3];
    const float* w1     = (const float*)d_in[4];
    const float* b1     = (const float*)d_in[5];
    const float* w2     = (const float*)d_in[6];
    const float* b2     = (const float*)d_in[7];
    const float* bw1    = (const float*)d_in[8];
    const float* bb1    = (const float*)d_in[9];
    const float* bw2    = (const float*)d_in[10];
    const float* bb2    = (const float*)d_in[11];
    float* out = (float*)d_out;

    pack_weights_kernel<<<1, 256>>>(b1, w2, b2, zbg, bw1, bb1);
    dim3 tgrid(HRES * HRES / 32, BATCH * 3);
    transpose_planes_kernel<<<tgrid, dim3(32, 8)>>>(planes);

    const int decode_blocks = NR * 6 / 4;   // 1 chunk per warp, 4 warps/block (R10 config)
    decode_kernel<<<decode_blocks, 128>>>(ro, rd, w1, 0);
    march_kernel<<<NR / 4, 128>>>();
    decode_kernel<<<decode_blocks, 128>>>(ro, rd, w1, 1);
    final_kernel<<<NR / 4, 128>>>(rd, bw1, bw2, bb2, out);
}

// round 13
// speedup vs baseline: 1.6452x; 1.0570x over previous
#include <cuda_runtime.h>
#include <math.h>

#define BATCH 4
#define RAYS  4096
#define NR    (BATCH * RAYS)
#define NCH   32
#define HRES  256
#define HPAD  258
#define PLSZ  (HPAD * HPAD * NCH)
#define SC    48
#define NI    48
#define NALL  96
#define STEPF ((3.3f - 2.25f) / 47.0f)

// Bordered transposed planes: (B,3,258,258,C); 1-px border stays zero.
__device__ float g_planesT[(size_t)BATCH * 3 * PLSZ];
__device__ float g_sigma[(size_t)NR * NALL];
__device__ float g_rgbb[(size_t)NR * NALL * NCH];
__device__ float g_zfine[(size_t)NR * NI];
// Packed decode weights: [0..511] f4 = w2p pairs, [512..527] f4 = wsig2,
// [528..543] f4 = b1 pairs, floats 2176..2207 = b2[1..32], 2208 = b2[0].
__device__ float4 g_wpack[560];
// Precomputed bg layer-1 partial: bb1[u] + sum_i zbg[b,i]*bw1[3+i][u]
__device__ float g_bgz[BATCH][64];

__device__ __forceinline__ float softplusf_fast(float x) {
    return fmaxf(x, 0.0f) + __logf(1.0f + __expf(-fabsf(x)));
}
__device__ __forceinline__ float sigmoidf_fast(float x) {
    return 1.0f / (1.0f + __expf(-x));
}
__device__ __forceinline__ float2 ffma2(float2 a, float2 b, float2 c) {
    unsigned long long ra = *reinterpret_cast<unsigned long long*>(&a);
    unsigned long long rb = *reinterpret_cast<unsigned long long*>(&b);
    unsigned long long rc = *reinterpret_cast<unsigned long long*>(&c);
    unsigned long long rd;
    asm("fma.rn.f32x2 %0, %1, %2, %3;" : "=l"(rd) : "l"(ra), "l"(rb), "l"(rc));
    return *reinterpret_cast<float2*>(&rd);
}

// ---------------------------------------------------------------------------
// Pack decode weights + precompute bg z-partial. 256 threads.
// ---------------------------------------------------------------------------
__global__ void pack_weights_kernel(const float* __restrict__ b1,
                                    const float* __restrict__ w2,
                                    const float* __restrict__ b2,
                                    const float* __restrict__ zbg,
                                    const float* __restrict__ bw1,
                                    const float* __restrict__ bb1) {
    const int tid = threadIdx.x;
    float2* wp2 = (float2*)g_wpack;
    float*  wpf = (float*)g_wpack;
    for (int i = tid; i < 1024; i += 256) {
        const int k = i >> 5, ch = i & 31;
        wp2[i] = make_float2(w2[(2 * k) * 33 + 1 + ch], w2[(2 * k + 1) * 33 + 1 + ch]);
    }
    if (tid < 32) {
        wp2[1024 + tid] = make_float2(w2[(2 * tid) * 33], w2[(2 * tid + 1) * 33]);
        wp2[1056 + tid] = ((const float2*)b1)[tid];
        wpf[2176 + tid] = b2[1 + tid];
    }
    if (tid == 0) wpf[2208] = b2[0];
    // bg z-partial: tid = b*64 + u
    {
        const int b = tid >> 6, u = tid & 63;
        float acc = bb1[u];
        #pragma unroll 4
        for (int i = 0; i < 64; i++)
            acc = fmaf(zbg[b * 64 + i], bw1[(3 + i) * 64 + u], acc);
        g_bgz[b][u] = acc;
    }
}

// ---------------------------------------------------------------------------
// Transpose (B,3,C,256,256) -> bordered (B,3,258,258,C)
// ---------------------------------------------------------------------------
__global__ void transpose_planes_kernel(const float* __restrict__ planes) {
    __shared__ float tile[32][33];
    const int bp  = blockIdx.y;
    const int hw0 = blockIdx.x * 32;
    const float* src = planes + (size_t)bp * NCH * HRES * HRES;
    #pragma unroll
    for (int c = threadIdx.y; c < 32; c += 8)
        tile[c][threadIdx.x] = src[(size_t)c * (HRES * HRES) + hw0 + threadIdx.x];
    __syncthreads();
    float* dst = g_planesT + (size_t)bp * PLSZ;
    #pragma unroll
    for (int r = threadIdx.y; r < 32; r += 8) {
        const int hw = hw0 + r;
        const int y = hw >> 8, x = hw & 255;
        dst[(size_t)((y + 1) * HPAD + (x + 1)) * NCH + threadIdx.x] = tile[threadIdx.x][r];
    }
}

// ---------------------------------------------------------------------------
// Decode: sample-parallel warp-GEMM. 1 warp = 8 samples of one ray.
// Gather re-mapped: lane = (sample, channel-group), float4 taps cover 4
// samples per instruction (4x fewer LDG + parallel address math).
// ---------------------------------------------------------------------------
__global__ __launch_bounds__(128, 6) void decode_kernel(
    const float* __restrict__ ro, const float* __restrict__ rd,
    const float* __restrict__ w1, const int fine)
{
    __shared__ __align__(16) float2 sw1p[32 * 32];
    __shared__ __align__(16) float2 sw2p[32 * 32];
    __shared__ __align__(16) float2 wsig2[32];
    __shared__ __align__(16) float2 sb1p[32];
    __shared__ float  sb2r[32];
    __shared__ float  sb2sig;
    __shared__ __align__(16) float sstage[4][1152];

    const int tid  = threadIdx.x;
    const int warp = tid >> 5;
    const int lane = tid & 31;

    {   // stage weights: contiguous float4 copies
        const float4* w1v4 = (const float4*)w1;
        float4* d1 = (float4*)sw1p;
        #pragma unroll
        for (int i = tid; i < 512; i += 128) d1[i] = w1v4[i];
        float4* d2 = (float4*)sw2p;
        #pragma unroll
        for (int i = tid; i < 512; i += 128) d2[i] = g_wpack[i];
        if (tid < 16) {
            ((float4*)wsig2)[tid] = g_wpack[512 + tid];
            ((float4*)sb1p)[tid]  = g_wpack[528 + tid];
        }
        const float* wpf = (const float*)g_wpack;
        if (tid < 32) sb2r[tid] = wpf[2176 + tid];
        if (tid == 0) sb2sig = wpf[2208];
    }
    __syncthreads();

    const int gw    = blockIdx.x * 4 + warp;
    const int ray   = gw / 6;
    const int sbase = (gw % 6) * 8;
    const int b     = ray >> 12;
    const int soff  = fine ? SC : 0;

    const float ox = __ldg(ro + ray * 3 + 0);
    const float oy = __ldg(ro + ray * 3 + 1);
    const float oz = __ldg(ro + ray * 3 + 2);
    const float dx = __ldg(rd + ray * 3 + 0);
    const float dy = __ldg(rd + ray * 3 + 1);
    const float dz = __ldg(rd + ray * 3 + 2);

    // premultiplied pixel-space ray constants: x_px = t*a + b
    const float axc = 256.0f * dx, bxc = fmaf(256.0f, ox, 127.5f);
    const float ayc = 256.0f * dy, byc = fmaf(256.0f, oy, 127.5f);
    const float azc = 256.0f * dz, bzc = fmaf(256.0f, oz, 127.5f);

    float* stg = sstage[warp];

    // --- gather 8 samples in 2 sub-passes of 4; lane=(s4, channel-group) ---
    {
        const int s4 = lane >> 3;       // sample within sub-pass (0..3)
        const int cg = lane & 7;        // channel group (4 channels)
        const float4* pb4 = (const float4*)g_planesT
                          + (size_t)(b * 3) * (PLSZ / 4) + (HPAD + 1) * 8 + cg;
        #pragma unroll
        for (int u = 0; u < 2; u++) {
            const int s = u * 4 + s4;
            float t;
            if (fine) t = __ldg(&g_zfine[(size_t)ray * NI + sbase + s]);
            else      t = 2.25f + ((float)(sbase + s) + 0.5f) * STEPF;
            const float X = fmaf(t, axc, bxc);
            const float Y = fmaf(t, ayc, byc);
            const float Z = fmaf(t, azc, bzc);
            float fx = 0.0f, fy = 0.0f, fz = 0.0f, fw = 0.0f;
            #pragma unroll
            for (int p = 0; p < 3; p++) {
                const float x = (p == 2) ? Z : X;
                const float y = (p == 0) ? Y : ((p == 1) ? Z : X);
                const float x0f = floorf(x), y0f = floorf(y);
                const float wx = x - x0f, wy = y - y0f;
                const int x0 = (int)x0f, y0 = (int)y0f;
                const int x0c = min(max(x0,     -1), 256);
                const int x1c = min(max(x0 + 1, -1), 256);
                const int y0c = min(max(y0,     -1), 256);
                const int y1c = min(max(y0 + 1, -1), 256);
                const float4* base = pb4 + (size_t)p * (HPAD * HPAD * 8);
                const int r0 = y0c * HPAD, r1 = y1c * HPAD;
                const float4 v00 = __ldg(base + (r0 + x0c) * 8);
                const float4 v10 = __ldg(base + (r0 + x1c) * 8);
                const float4 v01 = __ldg(base + (r1 + x0c) * 8);
                const float4 v11 = __ldg(base + (r1 + x1c) * 8);
                const float iwx = 1.0f - wx, iwy = 1.0f - wy;
                const float w00 = iwx * iwy, w10 = wx * iwy;
                const float w01 = iwx * wy,  w11 = wx * wy;
                fx = fmaf(v00.x, w00, fmaf(v10.x, w10, fmaf(v01.x, w01, fmaf(v11.x, w11, fx))));
                fy = fmaf(v00.y, w00, fmaf(v10.y, w10, fmaf(v01.y, w01, fmaf(v11.y, w11, fy))));
                fz = fmaf(v00.z, w00, fmaf(v10.z, w10, fmaf(v01.z, w01, fmaf(v11.z, w11, fz))));
                fw = fmaf(v00.w, w00, fmaf(v10.w, w10, fmaf(v01.w, w01, fmaf(v11.w, w11, fw))));
            }
            const float sc = (1.0f / 3.0f);
            stg[(4 * cg + 0) * 12 + s] = fx * sc;
            stg[(4 * cg + 1) * 12 + s] = fy * sc;
            stg[(4 * cg + 2) * 12 + s] = fz * sc;
            stg[(4 * cg + 3) * 12 + s] = fw * sc;
        }
    }
    __syncwarp();

    // --- hidden layer: lane owns units (2*lane, 2*lane+1), 8 samples ---
    float2 acc[8];
    {
        const float2 bp = sb1p[lane];
        #pragma unroll
        for (int s = 0; s < 8; s++) acc[s] = bp;
    }
    #pragma unroll 4
    for (int c = 0; c < 32; c++) {
        const float4 f03 = *(const float4*)(stg + c * 12);
        const float4 f47 = *(const float4*)(stg + c * 12 + 4);
        const float2 w = sw1p[c * 32 + lane];
        acc[0] = ffma2(make_float2(f03.x, f03.x), w, acc[0]);
        acc[1] = ffma2(make_float2(f03.y, f03.y), w, acc[1]);
        acc[2] = ffma2(make_float2(f03.z, f03.z), w, acc[2]);
        acc[3] = ffma2(make_float2(f03.w, f03.w), w, acc[3]);
        acc[4] = ffma2(make_float2(f47.x, f47.x), w, acc[4]);
        acc[5] = ffma2(make_float2(f47.y, f47.y), w, acc[5]);
        acc[6] = ffma2(make_float2(f47.z, f47.z), w, acc[6]);
        acc[7] = ffma2(make_float2(f47.w, f47.w), w, acc[7]);
    }
    float h0[8], h1[8];
    #pragma unroll
    for (int s = 0; s < 8; s++) {
        h0[s] = softplusf_fast(acc[s].x);
        h1[s] = softplusf_fast(acc[s].y);
    }

    // --- sigma partials + butterfly ---
    float p[8];
    {
        const float2 ws = wsig2[lane];
        #pragma unroll
        for (int s = 0; s < 8; s++) p[s] = fmaf(h0[s], ws.x, h1[s] * ws.y);
    }
    #pragma unroll
    for (int off = 16; off; off >>= 1) {
        #pragma unroll
        for (int s = 0; s < 8; s++)
            p[s] += __shfl_xor_sync(0xffffffffu, p[s], off);
    }

    __syncwarp();
    *(float4*)(stg + lane * 36 + 0)  = make_float4(h0[0], h1[0], h0[1], h1[1]);
    *(float4*)(stg + lane * 36 + 4)  = make_float4(h0[2], h1[2], h0[3], h1[3]);
    *(float4*)(stg + lane * 36 + 8)  = make_float4(h0[4], h1[4], h0[5], h1[5]);
    *(float4*)(stg + lane * 36 + 12) = make_float4(h0[6], h1[6], h0[7], h1[7]);
    __syncwarp();

    // --- output layer ---
    float2 o2[8];
    #pragma unroll
    for (int s = 0; s < 8; s++) o2[s] = make_float2(0.0f, 0.0f);
    #pragma unroll 4
    for (int k = 0; k < 32; k++) {
        const float2 w = sw2p[k * 32 + lane];
        const float4 q0 = *(const float4*)(stg + k * 36 + 0);
        const float4 q1 = *(const float4*)(stg + k * 36 + 4);
        const float4 q2 = *(const float4*)(stg + k * 36 + 8);
        const float4 q3 = *(const float4*)(stg + k * 36 + 12);
        o2[0] = ffma2(make_float2(q0.x, q0.y), w, o2[0]);
        o2[1] = ffma2(make_float2(q0.z, q0.w), w, o2[1]);
        o2[2] = ffma2(make_float2(q1.x, q1.y), w, o2[2]);
        o2[3] = ffma2(make_float2(q1.z, q1.w), w, o2[3]);
        o2[4] = ffma2(make_float2(q2.x, q2.y), w, o2[4]);
        o2[5] = ffma2(make_float2(q2.z, q2.w), w, o2[5]);
        o2[6] = ffma2(make_float2(q3.x, q3.y), w, o2[6]);
        o2[7] = ffma2(make_float2(q3.z, q3.w), w, o2[7]);
    }

    const float bb = sb2r[lane];
    float* grow = g_rgbb + ((size_t)ray * NALL + soff + sbase) * NCH + lane;
    #pragma unroll
    for (int s = 0; s < 8; s++)
        grow[s * NCH] = sigmoidf_fast(o2[s].x + o2[s].y + bb) * 1.002f - 0.001f;

    float myp = p[0];
    if (lane == 1) myp = p[1];
    if (lane == 2) myp = p[2];
    if (lane == 3) myp = p[3];
    if (lane == 4) myp = p[4];
    if (lane == 5) myp = p[5];
    if (lane == 6) myp = p[6];
    if (lane == 7) myp = p[7];
    if (lane < 8)
        g_sigma[(size_t)ray * NALL + soff + sbase + lane] = myp + sb2sig;
}

// ---------------------------------------------------------------------------
// March: warp-parallel predicated scans.
// ---------------------------------------------------------------------------
__global__ __launch_bounds__(128) void march_kernel() {
    __shared__ float salpha[4][47];
    __shared__ float swcl[4][47];
    __shared__ float swk[4][45];
    __shared__ float scdf[4][46];

    const int warp = threadIdx.x >> 5;
    const int lane = threadIdx.x & 31;
    const int ray  = blockIdx.x * 4 + warp;

    const float* sg = g_sigma + (size_t)ray * NALL;
    for (int i = lane; i < 47; i += 32) {
        const float dens = softplusf_fast(0.5f * (__ldg(sg + i) + __ldg(sg + i + 1)) - 1.0f);
        salpha[warp][i] = 1.0f - __expf(-dens * STEPF);
    }
    __syncwarp();

    {
        float Ta = 1.0f, Tb = 1.0f;
        #pragma unroll 4
        for (int j = 0; j < 46; j++) {
            const float fj = 1.0f - salpha[warp][j] + 1e-10f;
            if (j < lane)      Ta *= fj;
            if (j < lane + 32) Tb *= fj;
        }
        swcl[warp][lane] = salpha[warp][lane] * Ta;
        if (lane + 32 < 47)
            swcl[warp][lane + 32] = salpha[warp][lane + 32] * Tb;
    }
    __syncwarp();

    float ssum = 0.0f;
    #pragma unroll
    for (int kk = 0; kk < 2; kk++) {
        const int k = lane + kk * 32;
        if (k < 45) {
            const float a  = fmaxf(swcl[warp][k],     swcl[warp][k + 1]) + 0.01f;
            const float bb = fmaxf(swcl[warp][k + 1], swcl[warp][k + 2]) + 0.01f;
            const float v  = 0.5f * (a + bb) + 0.01f + 1e-5f;
            swk[warp][k] = v;
            ssum += v;
        }
    }
    #pragma unroll
    for (int off = 16; off; off >>= 1)
        ssum += __shfl_xor_sync(0xffffffffu, ssum, off);
    const float inv = 1.0f / ssum;
    __syncwarp();

    {
        float ca = 0.0f, cb = 0.0f;
        #pragma unroll 4
        for (int j = 0; j < 45; j++) {
            const float vj = swk[warp][j];
            if (j <= lane)      ca += vj;
            if (j <= lane + 32) cb += vj;
        }
        if (lane == 0) scdf[warp][0] = 0.0f;
        scdf[warp][lane + 1] = ca * inv;
        if (lane + 33 <= 45) scdf[warp][lane + 33] = cb * inv;
    }
    __syncwarp();

    for (int i = lane; i < NI; i += 32) {
        const float u = ((float)i + 0.5f) * (1.0f / 48.0f);
        int idx = 0;
        while (idx < 46 && scdf[warp][idx] <= u) idx++;
        int below = idx - 1; if (below < 0) below = 0; if (below > 45) below = 45;
        int above = idx;     if (above > 45) above = 45;
        const float cb = scdf[warp][below], ca = scdf[warp][above];
        float den = ca - cb; if (den < 1e-5f) den = 1.0f;
        const float bbv = 2.25f + ((float)below + 1.0f) * STEPF;
        const float bav = 2.25f + ((float)above + 1.0f) * STEPF;
        g_zfine[(size_t)ray * NI + i] = fmaf((u - cb) / den, bav - bbv, bbv);
    }
}

// ---------------------------------------------------------------------------
// Final: merge + parallel-scan march + cheap bg MLP + composite. 1 warp/ray.
// ---------------------------------------------------------------------------
__global__ __launch_bounds__(128) void final_kernel(
    const float* __restrict__ rd,
    const float* __restrict__ bw1, const float* __restrict__ bw2,
    const float* __restrict__ bb2, float* __restrict__ out)
{
    __shared__ float zall[4][NALL];
    __shared__ float sig[4][NALL];
    __shared__ unsigned char perm[4][NALL];
    __shared__ float alpha_s[4][NALL - 1];
    __shared__ float wall[4][NALL - 1];
    __shared__ float bgh[4][64];
    __shared__ __align__(16) float sbw2[64 * 32];

    const int tid  = threadIdx.x;
    const int warp = tid >> 5;
    const int lane = tid & 31;
    const int ray  = blockIdx.x * 4 + warp;
    const int b    = ray >> 12;

    // stage bw2 (8KB) once per block
    {
        const float4* src = (const float4*)bw2;
        float4* dst = (float4*)sbw2;
        #pragma unroll
        for (int i = tid; i < 512; i += 128) dst[i] = src[i];
    }

    const float dx = __ldg(rd + ray * 3 + 0);
    const float dy = __ldg(rd + ray * 3 + 1);
    const float dz = __ldg(rd + ray * 3 + 2);

    for (int i = lane; i < NALL; i += 32) {
        sig[warp][i] = __ldg(&g_sigma[(size_t)ray * NALL + i]);
        zall[warp][i] = (i < SC) ? (2.25f + ((float)i + 0.5f) * STEPF)
                                 : __ldg(&g_zfine[(size_t)ray * NI + i - SC]);
    }

    // --- bg layer 1: z-part precomputed (g_bgz), only 3 direction FMAs ---
    {
        float a0 = g_bgz[b][lane];
        float a1 = g_bgz[b][lane + 32];
        a0 = fmaf(dx, __ldg(bw1 + 0 * 64 + lane), a0);
        a1 = fmaf(dx, __ldg(bw1 + 0 * 64 + 32 + lane), a1);
        a0 = fmaf(dy, __ldg(bw1 + 1 * 64 + lane), a0);
        a1 = fmaf(dy, __ldg(bw1 + 1 * 64 + 32 + lane), a1);
        a0 = fmaf(dz, __ldg(bw1 + 2 * 64 + lane), a0);
        a1 = fmaf(dz, __ldg(bw1 + 2 * 64 + 32 + lane), a1);
        bgh[warp][lane]      = softplusf_fast(a0);
        bgh[warp][lane + 32] = softplusf_fast(a1);
    }
    __syncthreads();   // bw2 staged + bgh ready

    float bgc_r = __ldg(bb2 + lane);
    #pragma unroll 8
    for (int h = 0; h < 64; h++)
        bgc_r = fmaf(bgh[warp][h], sbw2[h * 32 + lane], bgc_r);
    bgc_r = sigmoidf_fast(bgc_r);
    __syncwarp();

    // --- stable merge by rank-counting ---
    for (int i = lane; i < SC; i += 32) {
        const float zv = zall[warp][i];
        int c = 0;
        #pragma unroll 8
        for (int k = 0; k < NI; k++) c += (zall[warp][SC + k] < zv) ? 1 : 0;
        perm[warp][i + c] = (unsigned char)i;
    }
    for (int j = lane; j < NI; j += 32) {
        const float zv = zall[warp][SC + j];
        int c = 0;
        #pragma unroll 8
        for (int k = 0; k < SC; k++) c += (zall[warp][k] <= zv) ? 1 : 0;
        perm[warp][j + c] = (unsigned char)(SC + j);
    }
    __syncwarp();

    for (int k = lane; k < NALL - 1; k += 32) {
        const float delta = zall[warp][perm[warp][k + 1]] - zall[warp][perm[warp][k]];
        const float dens  = softplusf_fast(0.5f * (sig[warp][perm[warp][k]] +
                                                   sig[warp][perm[warp][k + 1]]) - 1.0f);
        alpha_s[warp][k] = 1.0f - __expf(-dens * delta);
    }
    __syncwarp();

    // --- transmittance: predicated product scan over 95 factors ---
    float T0 = 1.0f, T1 = 1.0f, T2 = 1.0f, Tall = 1.0f;
    #pragma unroll 4
    for (int j = 0; j < NALL - 1; j++) {
        const float fj = 1.0f - alpha_s[warp][j] + 1e-10f;
        if (j < lane)      T0 *= fj;
        if (j < lane + 32) T1 *= fj;
        if (j < lane + 64) T2 *= fj;
        Tall *= fj;
    }
    float wt = 0.0f, dacc = 0.0f;
    {
        const int k = lane;
        const float w = alpha_s[warp][k] * T0;
        wall[warp][k] = w;
        wt += w;
        dacc = fmaf(w, 0.5f * (zall[warp][perm[warp][k]] + zall[warp][perm[warp][k + 1]]), dacc);
    }
    {
        const int k = lane + 32;
        const float w = alpha_s[warp][k] * T1;
        wall[warp][k] = w;
        wt += w;
        dacc = fmaf(w, 0.5f * (zall[warp][perm[warp][k]] + zall[warp][perm[warp][k + 1]]), dacc);
    }
    if (lane + 64 < NALL - 1) {
        const int k = lane + 64;
        const float w = alpha_s[warp][k] * T2;
        wall[warp][k] = w;
        wt += w;
        dacc = fmaf(w, 0.5f * (zall[warp][perm[warp][k]] + zall[warp][perm[warp][k + 1]]), dacc);
    }
    #pragma unroll
    for (int off = 16; off; off >>= 1) {
        wt   += __shfl_xor_sync(0xffffffffu, wt, off);
        dacc += __shfl_xor_sync(0xffffffffu, dacc, off);
    }
    __syncwarp();

    // --- composite (lane = channel) ---
    const size_t rbase = (size_t)ray * NALL * NCH + lane;
    float rprev = __ldg(&g_rgbb[rbase + (size_t)perm[warp][0] * NCH]);
    float acc = 0.0f;
    #pragma unroll 5
    for (int k = 0; k < NALL - 1; k++) {
        const float rnext = __ldg(&g_rgbb[rbase + (size_t)perm[warp][k + 1] * NCH]);
        acc = fmaf(wall[warp][k], 0.5f * (rprev + rnext), acc);
        rprev = rnext;
    }
    acc = fmaf(Tall, bgc_r, acc);

    float* out_rgb   = out;
    float* out_depth = out + (size_t)NR * 32;
    float* out_wsum  = out + (size_t)NR * 33;

    out_rgb[(size_t)ray * 32 + lane] = acc * 2.0f - 1.0f;
    if (lane == 0) {
        float dv = dacc / wt;
        if (dv != dv) dv = INFINITY;
        const float ZMIN = 2.25f + 0.5f  * STEPF;
        const float ZMAX = 2.25f + 47.5f * STEPF;
        dv = fminf(fmaxf(dv, ZMIN), ZMAX);
        out_depth[ray] = dv;
        out_wsum[ray]  = wt;
    }
}

// ---------------------------------------------------------------------------
extern "C" void kernel_launch(void* const* d_in, const int* in_sizes, int n_in,
                              void* d_out, int out_size) {
    const float* planes = (const float*)d_in[0];
    const float* ro     = (const float*)d_in[1];
    const float* rd     = (const float*)d_in[2];
    const float* zbg    = (const float*)d_in[3];
    const float* w1     = (const float*)d_in[4];
    const float* b1     = (const float*)d_in[5];
    const float* w2     = (const float*)d_in[6];
    const float* b2     = (const float*)d_in[7];
    const float* bw1    = (const float*)d_in[8];
    const float* bb1    = (const float*)d_in[9];
    const float* bw2    = (const float*)d_in[10];
    const float* bb2    = (const float*)d_in[11];
    float* out = (float*)d_out;

    pack_weights_kernel<<<1, 256>>>(b1, w2, b2, zbg, bw1, bb1);
    dim3 tgrid(HRES * HRES / 32, BATCH * 3);
    transpose_planes_kernel<<<tgrid, dim3(32, 8)>>>(planes);

    const int decode_blocks = NR * 6 / 4;
    decode_kernel<<<decode_blocks, 128>>>(ro, rd, w1, 0);
    march_kernel<<<NR / 4, 128>>>();
    decode_kernel<<<decode_blocks, 128>>>(ro, rd, w1, 1);
    final_kernel<<<NR / 4, 128>>>(rd, bw1, bw2, bb2, out);
}

// round 14
// speedup vs baseline: 1.6569x; 1.0071x over previous
#include <cuda_runtime.h>
#include <math.h>

#define BATCH 4
#define RAYS  4096
#define NR    (BATCH * RAYS)
#define NCH   32
#define HRES  256
#define HPAD  258
#define PLSZ  (HPAD * HPAD * NCH)
#define SC    48
#define NI    48
#define NALL  96
#define STEPF ((3.3f - 2.25f) / 47.0f)

// Bordered transposed planes: (B,3,258,258,C); 1-px border stays zero.
__device__ float g_planesT[(size_t)BATCH * 3 * PLSZ];
__device__ float g_sigma[(size_t)NR * NALL];
__device__ float g_rgbb[(size_t)NR * NALL * NCH];
__device__ float g_zfine[(size_t)NR * NI];
// Packed decode weights: [0..511] f4 = w2p pairs, [512..527] f4 = wsig2,
// [528..543] f4 = b1 pairs, floats 2176..2207 = b2[1..32], 2208 = b2[0].
__device__ float4 g_wpack[560];
// Precomputed bg layer-1 partial: bb1[u] + sum_i zbg[b,i]*bw1[3+i][u]
__device__ float g_bgz[BATCH][64];

__device__ __forceinline__ float softplusf_fast(float x) {
    return fmaxf(x, 0.0f) + __logf(1.0f + __expf(-fabsf(x)));
}
__device__ __forceinline__ float sigmoidf_fast(float x) {
    return 1.0f / (1.0f + __expf(-x));
}
__device__ __forceinline__ float2 ffma2(float2 a, float2 b, float2 c) {
    unsigned long long ra = *reinterpret_cast<unsigned long long*>(&a);
    unsigned long long rb = *reinterpret_cast<unsigned long long*>(&b);
    unsigned long long rc = *reinterpret_cast<unsigned long long*>(&c);
    unsigned long long rd;
    asm("fma.rn.f32x2 %0, %1, %2, %3;" : "=l"(rd) : "l"(ra), "l"(rb), "l"(rc));
    return *reinterpret_cast<float2*>(&rd);
}

// ---------------------------------------------------------------------------
// Pack decode weights + precompute bg z-partial. 256 threads.
// ---------------------------------------------------------------------------
__global__ void pack_weights_kernel(const float* __restrict__ b1,
                                    const float* __restrict__ w2,
                                    const float* __restrict__ b2,
                                    const float* __restrict__ zbg,
                                    const float* __restrict__ bw1,
                                    const float* __restrict__ bb1) {
    const int tid = threadIdx.x;
    float2* wp2 = (float2*)g_wpack;
    float*  wpf = (float*)g_wpack;
    for (int i = tid; i < 1024; i += 256) {
        const int k = i >> 5, ch = i & 31;
        wp2[i] = make_float2(w2[(2 * k) * 33 + 1 + ch], w2[(2 * k + 1) * 33 + 1 + ch]);
    }
    if (tid < 32) {
        wp2[1024 + tid] = make_float2(w2[(2 * tid) * 33], w2[(2 * tid + 1) * 33]);
        wp2[1056 + tid] = ((const float2*)b1)[tid];
        wpf[2176 + tid] = b2[1 + tid];
    }
    if (tid == 0) wpf[2208] = b2[0];
    // bg z-partial: tid = b*64 + u
    {
        const int b = tid >> 6, u = tid & 63;
        float acc = bb1[u];
        #pragma unroll 4
        for (int i = 0; i < 64; i++)
            acc = fmaf(zbg[b * 64 + i], bw1[(3 + i) * 64 + u], acc);
        g_bgz[b][u] = acc;
    }
}

// ---------------------------------------------------------------------------
// Transpose (B,3,C,256,256) -> bordered (B,3,258,258,C)
// ---------------------------------------------------------------------------
__global__ void transpose_planes_kernel(const float* __restrict__ planes) {
    __shared__ float tile[32][33];
    const int bp  = blockIdx.y;
    const int hw0 = blockIdx.x * 32;
    const float* src = planes + (size_t)bp * NCH * HRES * HRES;
    #pragma unroll
    for (int c = threadIdx.y; c < 32; c += 8)
        tile[c][threadIdx.x] = src[(size_t)c * (HRES * HRES) + hw0 + threadIdx.x];
    __syncthreads();
    float* dst = g_planesT + (size_t)bp * PLSZ;
    #pragma unroll
    for (int r = threadIdx.y; r < 32; r += 8) {
        const int hw = hw0 + r;
        const int y = hw >> 8, x = hw & 255;
        dst[(size_t)((y + 1) * HPAD + (x + 1)) * NCH + threadIdx.x] = tile[threadIdx.x][r];
    }
}

// ---------------------------------------------------------------------------
// Decode: sample-parallel warp-GEMM. 1 warp = 8 samples of one ray.
// Sigma computed + stored BEFORE output layer to shrink live ranges.
// ---------------------------------------------------------------------------
__global__ __launch_bounds__(128, 6) void decode_kernel(
    const float* __restrict__ ro, const float* __restrict__ rd,
    const float* __restrict__ w1, const int fine)
{
    __shared__ __align__(16) float2 sw1p[32 * 32];
    __shared__ __align__(16) float2 sw2p[32 * 32];
    __shared__ __align__(16) float2 wsig2[32];
    __shared__ __align__(16) float2 sb1p[32];
    __shared__ float  sb2r[32];
    __shared__ float  sb2sig;
    __shared__ __align__(16) float sstage[4][1152];

    const int tid  = threadIdx.x;
    const int warp = tid >> 5;
    const int lane = tid & 31;

    {   // stage weights: contiguous float4 copies
        const float4* w1v4 = (const float4*)w1;
        float4* d1 = (float4*)sw1p;
        #pragma unroll
        for (int i = tid; i < 512; i += 128) d1[i] = w1v4[i];
        float4* d2 = (float4*)sw2p;
        #pragma unroll
        for (int i = tid; i < 512; i += 128) d2[i] = g_wpack[i];
        if (tid < 16) {
            ((float4*)wsig2)[tid] = g_wpack[512 + tid];
            ((float4*)sb1p)[tid]  = g_wpack[528 + tid];
        }
        const float* wpf = (const float*)g_wpack;
        if (tid < 32) sb2r[tid] = wpf[2176 + tid];
        if (tid == 0) sb2sig = wpf[2208];
    }
    __syncthreads();

    const int gw    = blockIdx.x * 4 + warp;
    const int ray   = gw / 6;
    const int sbase = (gw % 6) * 8;
    const int b     = ray >> 12;
    const int soff  = fine ? SC : 0;

    const float ox = __ldg(ro + ray * 3 + 0);
    const float oy = __ldg(ro + ray * 3 + 1);
    const float oz = __ldg(ro + ray * 3 + 2);
    const float dx = __ldg(rd + ray * 3 + 0);
    const float dy = __ldg(rd + ray * 3 + 1);
    const float dz = __ldg(rd + ray * 3 + 2);

    // premultiplied pixel-space ray constants: x_px = t*a + b
    const float axc = 256.0f * dx, bxc = fmaf(256.0f, ox, 127.5f);
    const float ayc = 256.0f * dy, byc = fmaf(256.0f, oy, 127.5f);
    const float azc = 256.0f * dz, bzc = fmaf(256.0f, oz, 127.5f);

    float* stg = sstage[warp];

    // --- gather 8 samples in 2 sub-passes of 4; lane=(s4, channel-group) ---
    {
        const int s4 = lane >> 3;       // sample within sub-pass (0..3)
        const int cg = lane & 7;        // channel group (4 channels)
        const float4* pb4 = (const float4*)g_planesT
                          + (size_t)(b * 3) * (PLSZ / 4) + (HPAD + 1) * 8 + cg;
        #pragma unroll
        for (int u = 0; u < 2; u++) {
            const int s = u * 4 + s4;
            float t;
            if (fine) t = __ldg(&g_zfine[(size_t)ray * NI + sbase + s]);
            else      t = 2.25f + ((float)(sbase + s) + 0.5f) * STEPF;
            const float X = fmaf(t, axc, bxc);
            const float Y = fmaf(t, ayc, byc);
            const float Z = fmaf(t, azc, bzc);
            float2 fxy = make_float2(0.0f, 0.0f);
            float2 fzw = make_float2(0.0f, 0.0f);
            #pragma unroll
            for (int p = 0; p < 3; p++) {
                const float x = (p == 2) ? Z : X;
                const float y = (p == 0) ? Y : ((p == 1) ? Z : X);
                const float x0f = floorf(x), y0f = floorf(y);
                const float wx = x - x0f, wy = y - y0f;
                const int x0 = (int)x0f, y0 = (int)y0f;
                const int x0c = min(max(x0,     -1), 256);
                const int x1c = min(max(x0 + 1, -1), 256);
                const int y0c = min(max(y0,     -1), 256);
                const int y1c = min(max(y0 + 1, -1), 256);
                const float4* base = pb4 + (size_t)p * (HPAD * HPAD * 8);
                const int r0 = y0c * HPAD, r1 = y1c * HPAD;
                const float4 v00 = __ldg(base + (r0 + x0c) * 8);
                const float4 v10 = __ldg(base + (r0 + x1c) * 8);
                const float4 v01 = __ldg(base + (r1 + x0c) * 8);
                const float4 v11 = __ldg(base + (r1 + x1c) * 8);
                const float iwx = 1.0f - wx, iwy = 1.0f - wy;
                const float w00 = iwx * iwy, w10 = wx * iwy;
                const float w01 = iwx * wy,  w11 = wx * wy;
                const float2 w00p = make_float2(w00, w00);
                const float2 w10p = make_float2(w10, w10);
                const float2 w01p = make_float2(w01, w01);
                const float2 w11p = make_float2(w11, w11);
                fxy = ffma2(make_float2(v00.x, v00.y), w00p, fxy);
                fxy = ffma2(make_float2(v10.x, v10.y), w10p, fxy);
                fxy = ffma2(make_float2(v01.x, v01.y), w01p, fxy);
                fxy = ffma2(make_float2(v11.x, v11.y), w11p, fxy);
                fzw = ffma2(make_float2(v00.z, v00.w), w00p, fzw);
                fzw = ffma2(make_float2(v10.z, v10.w), w10p, fzw);
                fzw = ffma2(make_float2(v01.z, v01.w), w01p, fzw);
                fzw = ffma2(make_float2(v11.z, v11.w), w11p, fzw);
            }
            const float sc = (1.0f / 3.0f);
            stg[(4 * cg + 0) * 12 + s] = fxy.x * sc;
            stg[(4 * cg + 1) * 12 + s] = fxy.y * sc;
            stg[(4 * cg + 2) * 12 + s] = fzw.x * sc;
            stg[(4 * cg + 3) * 12 + s] = fzw.y * sc;
        }
    }
    __syncwarp();

    // --- hidden layer: lane owns units (2*lane, 2*lane+1), 8 samples ---
    float2 acc[8];
    {
        const float2 bp = sb1p[lane];
        #pragma unroll
        for (int s = 0; s < 8; s++) acc[s] = bp;
    }
    #pragma unroll 4
    for (int c = 0; c < 32; c++) {
        const float4 f03 = *(const float4*)(stg + c * 12);
        const float4 f47 = *(const float4*)(stg + c * 12 + 4);
        const float2 w = sw1p[c * 32 + lane];
        acc[0] = ffma2(make_float2(f03.x, f03.x), w, acc[0]);
        acc[1] = ffma2(make_float2(f03.y, f03.y), w, acc[1]);
        acc[2] = ffma2(make_float2(f03.z, f03.z), w, acc[2]);
        acc[3] = ffma2(make_float2(f03.w, f03.w), w, acc[3]);
        acc[4] = ffma2(make_float2(f47.x, f47.x), w, acc[4]);
        acc[5] = ffma2(make_float2(f47.y, f47.y), w, acc[5]);
        acc[6] = ffma2(make_float2(f47.z, f47.z), w, acc[6]);
        acc[7] = ffma2(make_float2(f47.w, f47.w), w, acc[7]);
    }
    float h0[8], h1[8];
    #pragma unroll
    for (int s = 0; s < 8; s++) {
        h0[s] = softplusf_fast(acc[s].x);
        h1[s] = softplusf_fast(acc[s].y);
    }

    // --- sigma: partials + butterfly + STORE NOW (frees p and h early) ---
    {
        float p[8];
        const float2 ws = wsig2[lane];
        #pragma unroll
        for (int s = 0; s < 8; s++) p[s] = fmaf(h0[s], ws.x, h1[s] * ws.y);
        #pragma unroll
        for (int off = 16; off; off >>= 1) {
            #pragma unroll
            for (int s = 0; s < 8; s++)
                p[s] += __shfl_xor_sync(0xffffffffu, p[s], off);
        }
        float myp = p[0];
        if (lane == 1) myp = p[1];
        if (lane == 2) myp = p[2];
        if (lane == 3) myp = p[3];
        if (lane == 4) myp = p[4];
        if (lane == 5) myp = p[5];
        if (lane == 6) myp = p[6];
        if (lane == 7) myp = p[7];
        if (lane < 8)
            g_sigma[(size_t)ray * NALL + soff + sbase + lane] = myp + sb2sig;
    }

    __syncwarp();
    *(float4*)(stg + lane * 36 + 0)  = make_float4(h0[0], h1[0], h0[1], h1[1]);
    *(float4*)(stg + lane * 36 + 4)  = make_float4(h0[2], h1[2], h0[3], h1[3]);
    *(float4*)(stg + lane * 36 + 8)  = make_float4(h0[4], h1[4], h0[5], h1[5]);
    *(float4*)(stg + lane * 36 + 12) = make_float4(h0[6], h1[6], h0[7], h1[7]);
    __syncwarp();

    // --- output layer (h0/h1 dead past here; only o2[8] live) ---
    float2 o2[8];
    #pragma unroll
    for (int s = 0; s < 8; s++) o2[s] = make_float2(0.0f, 0.0f);
    #pragma unroll 4
    for (int k = 0; k < 32; k++) {
        const float2 w = sw2p[k * 32 + lane];
        const float4 q0 = *(const float4*)(stg + k * 36 + 0);
        const float4 q1 = *(const float4*)(stg + k * 36 + 4);
        const float4 q2 = *(const float4*)(stg + k * 36 + 8);
        const float4 q3 = *(const float4*)(stg + k * 36 + 12);
        o2[0] = ffma2(make_float2(q0.x, q0.y), w, o2[0]);
        o2[1] = ffma2(make_float2(q0.z, q0.w), w, o2[1]);
        o2[2] = ffma2(make_float2(q1.x, q1.y), w, o2[2]);
        o2[3] = ffma2(make_float2(q1.z, q1.w), w, o2[3]);
        o2[4] = ffma2(make_float2(q2.x, q2.y), w, o2[4]);
        o2[5] = ffma2(make_float2(q2.z, q2.w), w, o2[5]);
        o2[6] = ffma2(make_float2(q3.x, q3.y), w, o2[6]);
        o2[7] = ffma2(make_float2(q3.z, q3.w), w, o2[7]);
    }

    const float bb = sb2r[lane];
    float* grow = g_rgbb + ((size_t)ray * NALL + soff + sbase) * NCH + lane;
    #pragma unroll
    for (int s = 0; s < 8; s++)
        grow[s * NCH] = sigmoidf_fast(o2[s].x + o2[s].y + bb) * 1.002f - 0.001f;
}

// ---------------------------------------------------------------------------
// March: warp-parallel predicated scans.
// ---------------------------------------------------------------------------
__global__ __launch_bounds__(128) void march_kernel() {
    __shared__ float salpha[4][47];
    __shared__ float swcl[4][47];
    __shared__ float swk[4][45];
    __shared__ float scdf[4][46];

    const int warp = threadIdx.x >> 5;
    const int lane = threadIdx.x & 31;
    const int ray  = blockIdx.x * 4 + warp;

    const float* sg = g_sigma + (size_t)ray * NALL;
    for (int i = lane; i < 47; i += 32) {
        const float dens = softplusf_fast(0.5f * (__ldg(sg + i) + __ldg(sg + i + 1)) - 1.0f);
        salpha[warp][i] = 1.0f - __expf(-dens * STEPF);
    }
    __syncwarp();

    {
        float Ta = 1.0f, Tb = 1.0f;
        #pragma unroll 4
        for (int j = 0; j < 46; j++) {
            const float fj = 1.0f - salpha[warp][j] + 1e-10f;
            if (j < lane)      Ta *= fj;
            if (j < lane + 32) Tb *= fj;
        }
        swcl[warp][lane] = salpha[warp][lane] * Ta;
        if (lane + 32 < 47)
            swcl[warp][lane + 32] = salpha[warp][lane + 32] * Tb;
    }
    __syncwarp();

    float ssum = 0.0f;
    #pragma unroll
    for (int kk = 0; kk < 2; kk++) {
        const int k = lane + kk * 32;
        if (k < 45) {
            const float a  = fmaxf(swcl[warp][k],     swcl[warp][k + 1]) + 0.01f;
            const float bb = fmaxf(swcl[warp][k + 1], swcl[warp][k + 2]) + 0.01f;
            const float v  = 0.5f * (a + bb) + 0.01f + 1e-5f;
            swk[warp][k] = v;
            ssum += v;
        }
    }
    #pragma unroll
    for (int off = 16; off; off >>= 1)
        ssum += __shfl_xor_sync(0xffffffffu, ssum, off);
    const float inv = 1.0f / ssum;
    __syncwarp();

    {
        float ca = 0.0f, cb = 0.0f;
        #pragma unroll 4
        for (int j = 0; j < 45; j++) {
            const float vj = swk[warp][j];
            if (j <= lane)      ca += vj;
            if (j <= lane + 32) cb += vj;
        }
        if (lane == 0) scdf[warp][0] = 0.0f;
        scdf[warp][lane + 1] = ca * inv;
        if (lane + 33 <= 45) scdf[warp][lane + 33] = cb * inv;
    }
    __syncwarp();

    for (int i = lane; i < NI; i += 32) {
        const float u = ((float)i + 0.5f) * (1.0f / 48.0f);
        int idx = 0;
        while (idx < 46 && scdf[warp][idx] <= u) idx++;
        int below = idx - 1; if (below < 0) below = 0; if (below > 45) below = 45;
        int above = idx;     if (above > 45) above = 45;
        const float cb = scdf[warp][below], ca = scdf[warp][above];
        float den = ca - cb; if (den < 1e-5f) den = 1.0f;
        const float bbv = 2.25f + ((float)below + 1.0f) * STEPF;
        const float bav = 2.25f + ((float)above + 1.0f) * STEPF;
        g_zfine[(size_t)ray * NI + i] = fmaf((u - cb) / den, bav - bbv, bbv);
    }
}

// ---------------------------------------------------------------------------
// Final: merge + parallel-scan march + cheap bg MLP + composite. 1 warp/ray.
// ---------------------------------------------------------------------------
__global__ __launch_bounds__(128) void final_kernel(
    const float* __restrict__ rd,
    const float* __restrict__ bw1, const float* __restrict__ bw2,
    const float* __restrict__ bb2, float* __restrict__ out)
{
    __shared__ float zall[4][NALL];
    __shared__ float sig[4][NALL];
    __shared__ unsigned char perm[4][NALL];
    __shared__ float alpha_s[4][NALL - 1];
    __shared__ float wall[4][NALL - 1];
    __shared__ float bgh[4][64];
    __shared__ __align__(16) float sbw2[64 * 32];

    const int tid  = threadIdx.x;
    const int warp = tid >> 5;
    const int lane = tid & 31;
    const int ray  = blockIdx.x * 4 + warp;
    const int b    = ray >> 12;

    // stage bw2 (8KB) once per block
    {
        const float4* src = (const float4*)bw2;
        float4* dst = (float4*)sbw2;
        #pragma unroll
        for (int i = tid; i < 512; i += 128) dst[i] = src[i];
    }

    const float dx = __ldg(rd + ray * 3 + 0);
    const float dy = __ldg(rd + ray * 3 + 1);
    const float dz = __ldg(rd + ray * 3 + 2);

    for (int i = lane; i < NALL; i += 32) {
        sig[warp][i] = __ldg(&g_sigma[(size_t)ray * NALL + i]);
        zall[warp][i] = (i < SC) ? (2.25f + ((float)i + 0.5f) * STEPF)
                                 : __ldg(&g_zfine[(size_t)ray * NI + i - SC]);
    }

    // --- bg layer 1: z-part precomputed (g_bgz), only 3 direction FMAs ---
    {
        float a0 = g_bgz[b][lane];
        float a1 = g_bgz[b][lane + 32];
        a0 = fmaf(dx, __ldg(bw1 + 0 * 64 + lane), a0);
        a1 = fmaf(dx, __ldg(bw1 + 0 * 64 + 32 + lane), a1);
        a0 = fmaf(dy, __ldg(bw1 + 1 * 64 + lane), a0);
        a1 = fmaf(dy, __ldg(bw1 + 1 * 64 + 32 + lane), a1);
        a0 = fmaf(dz, __ldg(bw1 + 2 * 64 + lane), a0);
        a1 = fmaf(dz, __ldg(bw1 + 2 * 64 + 32 + lane), a1);
        bgh[warp][lane]      = softplusf_fast(a0);
        bgh[warp][lane + 32] = softplusf_fast(a1);
    }
    __syncthreads();   // bw2 staged + bgh ready

    float bgc_r = __ldg(bb2 + lane);
    #pragma unroll 8
    for (int h = 0; h < 64; h++)
        bgc_r = fmaf(bgh[warp][h], sbw2[h * 32 + lane], bgc_r);
    bgc_r = sigmoidf_fast(bgc_r);
    __syncwarp();

    // --- stable merge by rank-counting ---
    for (int i = lane; i < SC; i += 32) {
        const float zv = zall[warp][i];
        int c = 0;
        #pragma unroll 8
        for (int k = 0; k < NI; k++) c += (zall[warp][SC + k] < zv) ? 1 : 0;
        perm[warp][i + c] = (unsigned char)i;
    }
    for (int j = lane; j < NI; j += 32) {
        const float zv = zall[warp][SC + j];
        int c = 0;
        #pragma unroll 8
        for (int k = 0; k < SC; k++) c += (zall[warp][k] <= zv) ? 1 : 0;
        perm[warp][j + c] = (unsigned char)(SC + j);
    }
    __syncwarp();

    for (int k = lane; k < NALL - 1; k += 32) {
        const float delta = zall[warp][perm[warp][k + 1]] - zall[warp][perm[warp][k]];
        const float dens  = softplusf_fast(0.5f * (sig[warp][perm[warp][k]] +
                                                   sig[warp][perm[warp][k + 1]]) - 1.0f);
        alpha_s[warp][k] = 1.0f - __expf(-dens * delta);
    }
    __syncwarp();

    // --- transmittance: predicated product scan over 95 factors ---
    float T0 = 1.0f, T1 = 1.0f, T2 = 1.0f, Tall = 1.0f;
    #pragma unroll 4
    for (int j = 0; j < NALL - 1; j++) {
        const float fj = 1.0f - alpha_s[warp][j] + 1e-10f;
        if (j < lane)      T0 *= fj;
        if (j < lane + 32) T1 *= fj;
        if (j < lane + 64) T2 *= fj;
        Tall *= fj;
    }
    float wt = 0.0f, dacc = 0.0f;
    {
        const int k = lane;
        const float w = alpha_s[warp][k] * T0;
        wall[warp][k] = w;
        wt += w;
        dacc = fmaf(w, 0.5f * (zall[warp][perm[warp][k]] + zall[warp][perm[warp][k + 1]]), dacc);
    }
    {
        const int k = lane + 32;
        const float w = alpha_s[warp][k] * T1;
        wall[warp][k] = w;
        wt += w;
        dacc = fmaf(w, 0.5f * (zall[warp][perm[warp][k]] + zall[warp][perm[warp][k + 1]]), dacc);
    }
    if (lane + 64 < NALL - 1) {
        const int k = lane + 64;
        const float w = alpha_s[warp][k] * T2;
        wall[warp][k] = w;
        wt += w;
        dacc = fmaf(w, 0.5f * (zall[warp][perm[warp][k]] + zall[warp][perm[warp][k + 1]]), dacc);
    }
    #pragma unroll
    for (int off = 16; off; off >>= 1) {
        wt   += __shfl_xor_sync(0xffffffffu, wt, off);
        dacc += __shfl_xor_sync(0xffffffffu, dacc, off);
    }
    __syncwarp();

    // --- composite (lane = channel) ---
    const size_t rbase = (size_t)ray * NALL * NCH + lane;
    float rprev = __ldg(&g_rgbb[rbase + (size_t)perm[warp][0] * NCH]);
    float acc = 0.0f;
    #pragma unroll 5
    for (int k = 0; k < NALL - 1; k++) {
        const float rnext = __ldg(&g_rgbb[rbase + (size_t)perm[warp][k + 1] * NCH]);
        acc = fmaf(wall[warp][k], 0.5f * (rprev + rnext), acc);
        rprev = rnext;
    }
    acc = fmaf(Tall, bgc_r, acc);

    float* out_rgb   = out;
    float* out_depth = out + (size_t)NR * 32;
    float* out_wsum  = out + (size_t)NR * 33;

    out_rgb[(size_t)ray * 32 + lane] = acc * 2.0f - 1.0f;
    if (lane == 0) {
        float dv = dacc / wt;
        if (dv != dv) dv = INFINITY;
        const float ZMIN = 2.25f + 0.5f  * STEPF;
        const float ZMAX = 2.25f + 47.5f * STEPF;
        dv = fminf(fmaxf(dv, ZMIN), ZMAX);
        out_depth[ray] = dv;
        out_wsum[ray]  = wt;
    }
}

// ---------------------------------------------------------------------------
extern "C" void kernel_launch(void* const* d_in, const int* in_sizes, int n_in,
                              void* d_out, int out_size) {
    const float* planes = (const float*)d_in[0];
    const float* ro     = (const float*)d_in[1];
    const float* rd     = (const float*)d_in[2];
    const float* zbg    = (const float*)d_in[3];
    const float* w1     = (const float*)d_in[4];
    const float* b1     = (const float*)d_in[5];
    const float* w2     = (const float*)d_in[6];
    const float* b2     = (const float*)d_in[7];
    const float* bw1    = (const float*)d_in[8];
    const float* bb1    = (const float*)d_in[9];
    const float* bw2    = (const float*)d_in[10];
    const float* bb2    = (const float*)d_in[11];
    float* out = (float*)d_out;

    pack_weights_kernel<<<1, 256>>>(b1, w2, b2, zbg, bw1, bb1);
    dim3 tgrid(HRES * HRES / 32, BATCH * 3);
    transpose_planes_kernel<<<tgrid, dim3(32, 8)>>>(planes);

    const int decode_blocks = NR * 6 / 4;
    decode_kernel<<<decode_blocks, 128>>>(ro, rd, w1, 0);
    march_kernel<<<NR / 4, 128>>>();
    decode_kernel<<<decode_blocks, 128>>>(ro, rd, w1, 1);
    final_kernel<<<NR / 4, 128>>>(rd, bw1, bw2, bb2, out);
}

// round 15
// speedup vs baseline: 1.6983x; 1.0250x over previous
#include <cuda_runtime.h>
#include <math.h>

#define BATCH 4
#define RAYS  4096
#define NR    (BATCH * RAYS)
#define NCH   32
#define HRES  256
#define HPAD  258
#define PLSZ  (HPAD * HPAD * NCH)
#define SC    48
#define NI    48
#define NALL  96
#define STEPF ((3.3f - 2.25f) / 47.0f)

// Bordered transposed planes: (B,3,258,258,C); 1-px border stays zero.
__device__ float g_planesT[(size_t)BATCH * 3 * PLSZ];
__device__ float g_sigma[(size_t)NR * NALL];
__device__ float g_rgbb[(size_t)NR * NALL * NCH];
__device__ float g_zfine[(size_t)NR * NI];
// Packed decode weights:
// f4[0..511]   = w2p pairs            f4[512..527] = wsig2
// f4[528..543] = b1 pairs             floats 2176..2207 = b2[1..32], 2208 = b2[0]
// f4[560..1071] = w1 pre-scaled by 1/3 (same element order as input w1)
__device__ float4 g_wpack[1072];
// Precomputed bg layer-1 partial: bb1[u] + sum_i zbg[b,i]*bw1[3+i][u]
__device__ float g_bgz[BATCH][64];

__device__ __forceinline__ float softplusf_fast(float x) {
    return fmaxf(x, 0.0f) + __logf(1.0f + __expf(-fabsf(x)));
}
__device__ __forceinline__ float sigmoidf_fast(float x) {
    return 1.0f / (1.0f + __expf(-x));
}
__device__ __forceinline__ float2 ffma2(float2 a, float2 b, float2 c) {
    unsigned long long ra = *reinterpret_cast<unsigned long long*>(&a);
    unsigned long long rb = *reinterpret_cast<unsigned long long*>(&b);
    unsigned long long rc = *reinterpret_cast<unsigned long long*>(&c);
    unsigned long long rd;
    asm("fma.rn.f32x2 %0, %1, %2, %3;" : "=l"(rd) : "l"(ra), "l"(rb), "l"(rc));
    return *reinterpret_cast<float2*>(&rd);
}

// ---------------------------------------------------------------------------
// Pack decode weights + precompute bg z-partial. 256 threads.
// ---------------------------------------------------------------------------
__global__ void pack_weights_kernel(const float* __restrict__ w1,
                                    const float* __restrict__ b1,
                                    const float* __restrict__ w2,
                                    const float* __restrict__ b2,
                                    const float* __restrict__ zbg,
                                    const float* __restrict__ bw1,
                                    const float* __restrict__ bb1) {
    const int tid = threadIdx.x;
    float2* wp2 = (float2*)g_wpack;
    float*  wpf = (float*)g_wpack;
    for (int i = tid; i < 1024; i += 256) {
        const int k = i >> 5, ch = i & 31;
        wp2[i] = make_float2(w2[(2 * k) * 33 + 1 + ch], w2[(2 * k + 1) * 33 + 1 + ch]);
    }
    if (tid < 32) {
        wp2[1024 + tid] = make_float2(w2[(2 * tid) * 33], w2[(2 * tid + 1) * 33]);
        wp2[1056 + tid] = ((const float2*)b1)[tid];
        wpf[2176 + tid] = b2[1 + tid];
    }
    if (tid == 0) wpf[2208] = b2[0];
    // w1 pre-scaled by 1/3 (feature mean folded into weights)
    {
        const float4* w1v4 = (const float4*)w1;
        const float sc = 1.0f / 3.0f;
        for (int i = tid; i < 512; i += 256) {
            float4 v = w1v4[i];
            v.x *= sc; v.y *= sc; v.z *= sc; v.w *= sc;
            g_wpack[560 + i] = v;
        }
    }
    // bg z-partial: tid = b*64 + u
    {
        const int b = tid >> 6, u = tid & 63;
        float acc = bb1[u];
        #pragma unroll 4
        for (int i = 0; i < 64; i++)
            acc = fmaf(zbg[b * 64 + i], bw1[(3 + i) * 64 + u], acc);
        g_bgz[b][u] = acc;
    }
}

// ---------------------------------------------------------------------------
// Transpose (B,3,C,256,256) -> bordered (B,3,258,258,C)
// ---------------------------------------------------------------------------
__global__ void transpose_planes_kernel(const float* __restrict__ planes) {
    __shared__ float tile[32][33];
    const int bp  = blockIdx.y;
    const int hw0 = blockIdx.x * 32;
    const float* src = planes + (size_t)bp * NCH * HRES * HRES;
    #pragma unroll
    for (int c = threadIdx.y; c < 32; c += 8)
        tile[c][threadIdx.x] = src[(size_t)c * (HRES * HRES) + hw0 + threadIdx.x];
    __syncthreads();
    float* dst = g_planesT + (size_t)bp * PLSZ;
    #pragma unroll
    for (int r = threadIdx.y; r < 32; r += 8) {
        const int hw = hw0 + r;
        const int y = hw >> 8, x = hw & 255;
        dst[(size_t)((y + 1) * HPAD + (x + 1)) * NCH + threadIdx.x] = tile[threadIdx.x][r];
    }
}

// ---------------------------------------------------------------------------
// Decode: sample-parallel warp-GEMM. 1 warp = 8 samples of one ray.
// ---------------------------------------------------------------------------
__global__ __launch_bounds__(128, 6) void decode_kernel(
    const float* __restrict__ ro, const float* __restrict__ rd, const int fine)
{
    __shared__ __align__(16) float2 sw1p[32 * 32];
    __shared__ __align__(16) float2 sw2p[32 * 32];
    __shared__ __align__(16) float2 wsig2[32];
    __shared__ __align__(16) float2 sb1p[32];
    __shared__ float  sb2r[32];
    __shared__ float  sb2sig;
    __shared__ __align__(16) float sstage[4][1152];

    const int tid  = threadIdx.x;
    const int warp = tid >> 5;
    const int lane = tid & 31;

    {   // stage weights: contiguous float4 copies from g_wpack
        float4* d1 = (float4*)sw1p;
        #pragma unroll
        for (int i = tid; i < 512; i += 128) d1[i] = g_wpack[560 + i];
        float4* d2 = (float4*)sw2p;
        #pragma unroll
        for (int i = tid; i < 512; i += 128) d2[i] = g_wpack[i];
        if (tid < 16) {
            ((float4*)wsig2)[tid] = g_wpack[512 + tid];
            ((float4*)sb1p)[tid]  = g_wpack[528 + tid];
        }
        const float* wpf = (const float*)g_wpack;
        if (tid < 32) sb2r[tid] = wpf[2176 + tid];
        if (tid == 0) sb2sig = wpf[2208];
    }
    __syncthreads();

    const int gw    = blockIdx.x * 4 + warp;
    const int ray   = gw / 6;
    const int sbase = (gw % 6) * 8;
    const int b     = ray >> 12;
    const int soff  = fine ? SC : 0;

    const float ox = __ldg(ro + ray * 3 + 0);
    const float oy = __ldg(ro + ray * 3 + 1);
    const float oz = __ldg(ro + ray * 3 + 2);
    const float dx = __ldg(rd + ray * 3 + 0);
    const float dy = __ldg(rd + ray * 3 + 1);
    const float dz = __ldg(rd + ray * 3 + 2);

    // premultiplied pixel-space ray constants: x_px = t*a + b
    const float axc = 256.0f * dx, bxc = fmaf(256.0f, ox, 127.5f);
    const float ayc = 256.0f * dy, byc = fmaf(256.0f, oy, 127.5f);
    const float azc = 256.0f * dz, bzc = fmaf(256.0f, oz, 127.5f);

    float* stg = sstage[warp];

    // --- gather 8 samples in 2 sub-passes of 4; lane=(s4, channel-group) ---
    {
        const int s4 = lane >> 3;       // sample within sub-pass (0..3)
        const int cg = lane & 7;        // channel group (4 channels)
        const float4* pb4 = (const float4*)g_planesT
                          + (size_t)(b * 3) * (PLSZ / 4) + (HPAD + 1) * 8 + cg;
        #pragma unroll
        for (int u = 0; u < 2; u++) {
            const int s = u * 4 + s4;
            float t;
            if (fine) t = __ldg(&g_zfine[(size_t)ray * NI + sbase + s]);
            else      t = 2.25f + ((float)(sbase + s) + 0.5f) * STEPF;
            const float X = fmaf(t, axc, bxc);
            const float Y = fmaf(t, ayc, byc);
            const float Z = fmaf(t, azc, bzc);
            float2 fxy = make_float2(0.0f, 0.0f);
            float2 fzw = make_float2(0.0f, 0.0f);
            #pragma unroll
            for (int p = 0; p < 3; p++) {
                const float x = (p == 2) ? Z : X;
                const float y = (p == 0) ? Y : ((p == 1) ? Z : X);
                const float x0f = floorf(x), y0f = floorf(y);
                const float wx = x - x0f, wy = y - y0f;
                const int x0 = (int)x0f, y0 = (int)y0f;
                const int x0c = min(max(x0,     -1), 256);
                const int x1c = min(max(x0 + 1, -1), 256);
                const int y0c = min(max(y0,     -1), 256);
                const int y1c = min(max(y0 + 1, -1), 256);
                const float4* base = pb4 + (size_t)p * (HPAD * HPAD * 8);
                const int r0 = y0c * HPAD, r1 = y1c * HPAD;
                const float4 v00 = __ldg(base + (r0 + x0c) * 8);
                const float4 v10 = __ldg(base + (r0 + x1c) * 8);
                const float4 v01 = __ldg(base + (r1 + x0c) * 8);
                const float4 v11 = __ldg(base + (r1 + x1c) * 8);
                const float iwx = 1.0f - wx, iwy = 1.0f - wy;
                const float w00 = iwx * iwy, w10 = wx * iwy;
                const float w01 = iwx * wy,  w11 = wx * wy;
                const float2 w00p = make_float2(w00, w00);
                const float2 w10p = make_float2(w10, w10);
                const float2 w01p = make_float2(w01, w01);
                const float2 w11p = make_float2(w11, w11);
                fxy = ffma2(make_float2(v00.x, v00.y), w00p, fxy);
                fxy = ffma2(make_float2(v10.x, v10.y), w10p, fxy);
                fxy = ffma2(make_float2(v01.x, v01.y), w01p, fxy);
                fxy = ffma2(make_float2(v11.x, v11.y), w11p, fxy);
                fzw = ffma2(make_float2(v00.z, v00.w), w00p, fzw);
                fzw = ffma2(make_float2(v10.z, v10.w), w10p, fzw);
                fzw = ffma2(make_float2(v01.z, v01.w), w01p, fzw);
                fzw = ffma2(make_float2(v11.z, v11.w), w11p, fzw);
            }
            // raw sums staged; the 1/3 mean is folded into w1 (and feat only
            // ever feeds the MLP through w1)
            stg[(4 * cg + 0) * 12 + s] = fxy.x;
            stg[(4 * cg + 1) * 12 + s] = fxy.y;
            stg[(4 * cg + 2) * 12 + s] = fzw.x;
            stg[(4 * cg + 3) * 12 + s] = fzw.y;
        }
    }
    __syncwarp();

    // --- hidden layer: lane owns units (2*lane, 2*lane+1), 8 samples ---
    float2 acc[8];
    {
        const float2 bp = sb1p[lane];
        #pragma unroll
        for (int s = 0; s < 8; s++) acc[s] = bp;
    }
    #pragma unroll 8
    for (int c = 0; c < 32; c++) {
        const float4 f03 = *(const float4*)(stg + c * 12);
        const float4 f47 = *(const float4*)(stg + c * 12 + 4);
        const float2 w = sw1p[c * 32 + lane];
        acc[0] = ffma2(make_float2(f03.x, f03.x), w, acc[0]);
        acc[1] = ffma2(make_float2(f03.y, f03.y), w, acc[1]);
        acc[2] = ffma2(make_float2(f03.z, f03.z), w, acc[2]);
        acc[3] = ffma2(make_float2(f03.w, f03.w), w, acc[3]);
        acc[4] = ffma2(make_float2(f47.x, f47.x), w, acc[4]);
        acc[5] = ffma2(make_float2(f47.y, f47.y), w, acc[5]);
        acc[6] = ffma2(make_float2(f47.z, f47.z), w, acc[6]);
        acc[7] = ffma2(make_float2(f47.w, f47.w), w, acc[7]);
    }
    float h0[8], h1[8];
    #pragma unroll
    for (int s = 0; s < 8; s++) {
        h0[s] = softplusf_fast(acc[s].x);
        h1[s] = softplusf_fast(acc[s].y);
    }

    // --- sigma: partials + lane-exchange tree reduction (9 shfl total) ---
    {
        float p[8];
        const float2 ws = wsig2[lane];
        #pragma unroll
        for (int s = 0; s < 8; s++) p[s] = fmaf(h0[s], ws.x, h1[s] * ws.y);

        // step mask=16: 8 values -> 4 (value bit worth 4)
        #pragma unroll
        for (int i = 0; i < 4; i++) {
            const float send = (lane & 16) ? p[i] : p[i + 4];
            const float recv = __shfl_xor_sync(0xffffffffu, send, 16);
            p[i] = ((lane & 16) ? p[i + 4] : p[i]) + recv;
        }
        // step mask=8: 4 -> 2 (value bit worth 2)
        #pragma unroll
        for (int i = 0; i < 2; i++) {
            const float send = (lane & 8) ? p[i] : p[i + 2];
            const float recv = __shfl_xor_sync(0xffffffffu, send, 8);
            p[i] = ((lane & 8) ? p[i + 2] : p[i]) + recv;
        }
        // step mask=4: 2 -> 1 (value bit worth 1)
        {
            const float send = (lane & 4) ? p[0] : p[1];
            const float recv = __shfl_xor_sync(0xffffffffu, send, 4);
            p[0] = ((lane & 4) ? p[1] : p[0]) + recv;
        }
        // finish reduction over lane bits 1,0
        p[0] += __shfl_xor_sync(0xffffffffu, p[0], 2);
        p[0] += __shfl_xor_sync(0xffffffffu, p[0], 1);
        // lane L (L%4==0) holds S[s] with s = L>>2
        if ((lane & 3) == 0)
            g_sigma[(size_t)ray * NALL + soff + sbase + (lane >> 2)] = p[0] + sb2sig;
    }

    __syncwarp();
    *(float4*)(stg + lane * 36 + 0)  = make_float4(h0[0], h1[0], h0[1], h1[1]);
    *(float4*)(stg + lane * 36 + 4)  = make_float4(h0[2], h1[2], h0[3], h1[3]);
    *(float4*)(stg + lane * 36 + 8)  = make_float4(h0[4], h1[4], h0[5], h1[5]);
    *(float4*)(stg + lane * 36 + 12) = make_float4(h0[6], h1[6], h0[7], h1[7]);
    __syncwarp();

    // --- output layer (only o2[8] live) ---
    float2 o2[8];
    #pragma unroll
    for (int s = 0; s < 8; s++) o2[s] = make_float2(0.0f, 0.0f);
    #pragma unroll 8
    for (int k = 0; k < 32; k++) {
        const float2 w = sw2p[k * 32 + lane];
        const float4 q0 = *(const float4*)(stg + k * 36 + 0);
        const float4 q1 = *(const float4*)(stg + k * 36 + 4);
        const float4 q2 = *(const float4*)(stg + k * 36 + 8);
        const float4 q3 = *(const float4*)(stg + k * 36 + 12);
        o2[0] = ffma2(make_float2(q0.x, q0.y), w, o2[0]);
        o2[1] = ffma2(make_float2(q0.z, q0.w), w, o2[1]);
        o2[2] = ffma2(make_float2(q1.x, q1.y), w, o2[2]);
        o2[3] = ffma2(make_float2(q1.z, q1.w), w, o2[3]);
        o2[4] = ffma2(make_float2(q2.x, q2.y), w, o2[4]);
        o2[5] = ffma2(make_float2(q2.z, q2.w), w, o2[5]);
        o2[6] = ffma2(make_float2(q3.x, q3.y), w, o2[6]);
        o2[7] = ffma2(make_float2(q3.z, q3.w), w, o2[7]);
    }

    const float bb = sb2r[lane];
    float* grow = g_rgbb + ((size_t)ray * NALL + soff + sbase) * NCH + lane;
    #pragma unroll
    for (int s = 0; s < 8; s++)
        grow[s * NCH] = sigmoidf_fast(o2[s].x + o2[s].y + bb) * 1.002f - 0.001f;
}

// ---------------------------------------------------------------------------
// March: warp-parallel predicated scans.
// ---------------------------------------------------------------------------
__global__ __launch_bounds__(128) void march_kernel() {
    __shared__ float salpha[4][47];
    __shared__ float swcl[4][47];
    __shared__ float swk[4][45];
    __shared__ float scdf[4][46];

    const int warp = threadIdx.x >> 5;
    const int lane = threadIdx.x & 31;
    const int ray  = blockIdx.x * 4 + warp;

    const float* sg = g_sigma + (size_t)ray * NALL;
    for (int i = lane; i < 47; i += 32) {
        const float dens = softplusf_fast(0.5f * (__ldg(sg + i) + __ldg(sg + i + 1)) - 1.0f);
        salpha[warp][i] = 1.0f - __expf(-dens * STEPF);
    }
    __syncwarp();

    {
        float Ta = 1.0f, Tb = 1.0f;
        #pragma unroll 4
        for (int j = 0; j < 46; j++) {
            const float fj = 1.0f - salpha[warp][j] + 1e-10f;
            if (j < lane)      Ta *= fj;
            if (j < lane + 32) Tb *= fj;
        }
        swcl[warp][lane] = salpha[warp][lane] * Ta;
        if (lane + 32 < 47)
            swcl[warp][lane + 32] = salpha[warp][lane + 32] * Tb;
    }
    __syncwarp();

    float ssum = 0.0f;
    #pragma unroll
    for (int kk = 0; kk < 2; kk++) {
        const int k = lane + kk * 32;
        if (k < 45) {
            const float a  = fmaxf(swcl[warp][k],     swcl[warp][k + 1]) + 0.01f;
            const float bb = fmaxf(swcl[warp][k + 1], swcl[warp][k + 2]) + 0.01f;
            const float v  = 0.5f * (a + bb) + 0.01f + 1e-5f;
            swk[warp][k] = v;
            ssum += v;
        }
    }
    #pragma unroll
    for (int off = 16; off; off >>= 1)
        ssum += __shfl_xor_sync(0xffffffffu, ssum, off);
    const float inv = 1.0f / ssum;
    __syncwarp();

    {
        float ca = 0.0f, cb = 0.0f;
        #pragma unroll 4
        for (int j = 0; j < 45; j++) {
            const float vj = swk[warp][j];
            if (j <= lane)      ca += vj;
            if (j <= lane + 32) cb += vj;
        }
        if (lane == 0) scdf[warp][0] = 0.0f;
        scdf[warp][lane + 1] = ca * inv;
        if (lane + 33 <= 45) scdf[warp][lane + 33] = cb * inv;
    }
    __syncwarp();

    for (int i = lane; i < NI; i += 32) {
        const float u = ((float)i + 0.5f) * (1.0f / 48.0f);
        int idx = 0;
        while (idx < 46 && scdf[warp][idx] <= u) idx++;
        int below = idx - 1; if (below < 0) below = 0; if (below > 45) below = 45;
        int above = idx;     if (above > 45) above = 45;
        const float cb = scdf[warp][below], ca = scdf[warp][above];
        float den = ca - cb; if (den < 1e-5f) den = 1.0f;
        const float bbv = 2.25f + ((float)below + 1.0f) * STEPF;
        const float bav = 2.25f + ((float)above + 1.0f) * STEPF;
        g_zfine[(size_t)ray * NI + i] = fmaf((u - cb) / den, bav - bbv, bbv);
    }
}

// ---------------------------------------------------------------------------
// Final: merge + parallel-scan march + cheap bg MLP + composite. 1 warp/ray.
// ---------------------------------------------------------------------------
__global__ __launch_bounds__(128) void final_kernel(
    const float* __restrict__ rd,
    const float* __restrict__ bw1, const float* __restrict__ bw2,
    const float* __restrict__ bb2, float* __restrict__ out)
{
    __shared__ float zall[4][NALL];
    __shared__ float sig[4][NALL];
    __shared__ unsigned char perm[4][NALL];
    __shared__ float alpha_s[4][NALL - 1];
    __shared__ float wall[4][NALL - 1];
    __shared__ float bgh[4][64];
    __shared__ __align__(16) float sbw2[64 * 32];

    const int tid  = threadIdx.x;
    const int warp = tid >> 5;
    const int lane = tid & 31;
    const int ray  = blockIdx.x * 4 + warp;
    const int b    = ray >> 12;

    // stage bw2 (8KB) once per block
    {
        const float4* src = (const float4*)bw2;
        float4* dst = (float4*)sbw2;
        #pragma unroll
        for (int i = tid; i < 512; i += 128) dst[i] = src[i];
    }

    const float dx = __ldg(rd + ray * 3 + 0);
    const float dy = __ldg(rd + ray * 3 + 1);
    const float dz = __ldg(rd + ray * 3 + 2);

    for (int i = lane; i < NALL; i += 32) {
        sig[warp][i] = __ldg(&g_sigma[(size_t)ray * NALL + i]);
        zall[warp][i] = (i < SC) ? (2.25f + ((float)i + 0.5f) * STEPF)
                                 : __ldg(&g_zfine[(size_t)ray * NI + i - SC]);
    }

    // --- bg layer 1: z-part precomputed (g_bgz), only 3 direction FMAs ---
    {
        float a0 = g_bgz[b][lane];
        float a1 = g_bgz[b][lane + 32];
        a0 = fmaf(dx, __ldg(bw1 + 0 * 64 + lane), a0);
        a1 = fmaf(dx, __ldg(bw1 + 0 * 64 + 32 + lane), a1);
        a0 = fmaf(dy, __ldg(bw1 + 1 * 64 + lane), a0);
        a1 = fmaf(dy, __ldg(bw1 + 1 * 64 + 32 + lane), a1);
        a0 = fmaf(dz, __ldg(bw1 + 2 * 64 + lane), a0);
        a1 = fmaf(dz, __ldg(bw1 + 2 * 64 + 32 + lane), a1);
        bgh[warp][lane]      = softplusf_fast(a0);
        bgh[warp][lane + 32] = softplusf_fast(a1);
    }
    __syncthreads();   // bw2 staged + bgh ready

    float bgc_r = __ldg(bb2 + lane);
    #pragma unroll 8
    for (int h = 0; h < 64; h++)
        bgc_r = fmaf(bgh[warp][h], sbw2[h * 32 + lane], bgc_r);
    bgc_r = sigmoidf_fast(bgc_r);
    __syncwarp();

    // --- stable merge by rank-counting ---
    for (int i = lane; i < SC; i += 32) {
        const float zv = zall[warp][i];
        int c = 0;
        #pragma unroll 8
        for (int k = 0; k < NI; k++) c += (zall[warp][SC + k] < zv) ? 1 : 0;
        perm[warp][i + c] = (unsigned char)i;
    }
    for (int j = lane; j < NI; j += 32) {
        const float zv = zall[warp][SC + j];
        int c = 0;
        #pragma unroll 8
        for (int k = 0; k < SC; k++) c += (zall[warp][k] <= zv) ? 1 : 0;
        perm[warp][j + c] = (unsigned char)(SC + j);
    }
    __syncwarp();

    for (int k = lane; k < NALL - 1; k += 32) {
        const float delta = zall[warp][perm[warp][k + 1]] - zall[warp][perm[warp][k]];
        const float dens  = softplusf_fast(0.5f * (sig[warp][perm[warp][k]] +
                                                   sig[warp][perm[warp][k + 1]]) - 1.0f);
        alpha_s[warp][k] = 1.0f - __expf(-dens * delta);
    }
    __syncwarp();

    // --- transmittance: predicated product scan over 95 factors ---
    float T0 = 1.0f, T1 = 1.0f, T2 = 1.0f, Tall = 1.0f;
    #pragma unroll 4
    for (int j = 0; j < NALL - 1; j++) {
        const float fj = 1.0f - alpha_s[warp][j] + 1e-10f;
        if (j < lane)      T0 *= fj;
        if (j < lane + 32) T1 *= fj;
        if (j < lane + 64) T2 *= fj;
        Tall *= fj;
    }
    float wt = 0.0f, dacc = 0.0f;
    {
        const int k = lane;
        const float w = alpha_s[warp][k] * T0;
        wall[warp][k] = w;
        wt += w;
        dacc = fmaf(w, 0.5f * (zall[warp][perm[warp][k]] + zall[warp][perm[warp][k + 1]]), dacc);
    }
    {
        const int k = lane + 32;
        const float w = alpha_s[warp][k] * T1;
        wall[warp][k] = w;
        wt += w;
        dacc = fmaf(w, 0.5f * (zall[warp][perm[warp][k]] + zall[warp][perm[warp][k + 1]]), dacc);
    }
    if (lane + 64 < NALL - 1) {
        const int k = lane + 64;
        const float w = alpha_s[warp][k] * T2;
        wall[warp][k] = w;
        wt += w;
        dacc = fmaf(w, 0.5f * (zall[warp][perm[warp][k]] + zall[warp][perm[warp][k + 1]]), dacc);
    }
    #pragma unroll
    for (int off = 16; off; off >>= 1) {
        wt   += __shfl_xor_sync(0xffffffffu, wt, off);
        dacc += __shfl_xor_sync(0xffffffffu, dacc, off);
    }
    __syncwarp();

    // --- composite (lane = channel) ---
    const size_t rbase = (size_t)ray * NALL * NCH + lane;
    float rprev = __ldg(&g_rgbb[rbase + (size_t)perm[warp][0] * NCH]);
    float acc = 0.0f;
    #pragma unroll 5
    for (int k = 0; k < NALL - 1; k++) {
        const float rnext = __ldg(&g_rgbb[rbase + (size_t)perm[warp][k + 1] * NCH]);
        acc = fmaf(wall[warp][k], 0.5f * (rprev + rnext), acc);
        rprev = rnext;
    }
    acc = fmaf(Tall, bgc_r, acc);

    float* out_rgb   = out;
    float* out_depth = out + (size_t)NR * 32;
    float* out_wsum  = out + (size_t)NR * 33;

    out_rgb[(size_t)ray * 32 + lane] = acc * 2.0f - 1.0f;
    if (lane == 0) {
        float dv = dacc / wt;
        if (dv != dv) dv = INFINITY;
        const float ZMIN = 2.25f + 0.5f  * STEPF;
        const float ZMAX = 2.25f + 47.5f * STEPF;
        dv = fminf(fmaxf(dv, ZMIN), ZMAX);
        out_depth[ray] = dv;
        out_wsum[ray]  = wt;
    }
}

// ---------------------------------------------------------------------------
extern "C" void kernel_launch(void* const* d_in, const int* in_sizes, int n_in,
                              void* d_out, int out_size) {
    const float* planes = (const float*)d_in[0];
    const float* ro     = (const float*)d_in[1];
    const float* rd     = (const float*)d_in[2];
    const float* zbg    = (const float*)d_in[3];
    const float* w1     = (const float*)d_in[4];
    const float* b1     = (const float*)d_in[5];
    const float* w2     = (const float*)d_in[6];
    const float* b2     = (const float*)d_in[7];
    const float* bw1    = (const float*)d_in[8];
    const float* bb1    = (const float*)d_in[9];
    const float* bw2    = (const float*)d_in[10];
    const float* bb2    = (const float*)d_in[11];
    float* out = (float*)d_out;

    pack_weights_kernel<<<1, 256>>>(w1, b1, w2, b2, zbg, bw1, bb1);
    dim3 tgrid(HRES * HRES / 32, BATCH * 3);
    transpose_planes_kernel<<<tgrid, dim3(32, 8)>>>(planes);

    const int decode_blocks = NR * 6 / 4;
    decode_kernel<<<decode_blocks, 128>>>(ro, rd, 0);
    march_kernel<<<NR / 4, 128>>>();
    decode_kernel<<<decode_blocks, 128>>>(ro, rd, 1);
    final_kernel<<<NR / 4, 128>>>(rd, bw1, bw2, bb2, out);
}

// round 16
// speedup vs baseline: 1.7513x; 1.0312x over previous
#include <cuda_runtime.h>
#include <cuda_fp16.h>
#include <math.h>

#define BATCH 4
#define RAYS  4096
#define NR    (BATCH * RAYS)
#define NCH   32
#define HRES  256
#define HPAD  258
#define PLSZ  (HPAD * HPAD * NCH)
#define SC    48
#define NI    48
#define NALL  96
#define STEPF ((3.3f - 2.25f) / 47.0f)

// Bordered transposed planes: (B,3,258,258,C); 1-px border stays zero.
__device__ float g_planesT[(size_t)BATCH * 3 * PLSZ];
__device__ float g_sigma[(size_t)NR * NALL];
__device__ __half g_rgbh[(size_t)NR * NALL * NCH];   // rgb scratch in half
__device__ float g_zfine[(size_t)NR * NI];
// Packed decode weights:
// f4[0..511]   = w2p pairs            f4[512..527] = wsig2
// f4[528..543] = b1 pairs             floats 2176..2207 = b2[1..32], 2208 = b2[0]
// f4[560..1071] = w1 pre-scaled by 1/3
__device__ float4 g_wpack[1072];
// Precomputed bg layer-1 partial: bb1[u] + sum_i zbg[b,i]*bw1[3+i][u]
__device__ float g_bgz[BATCH][64];

__device__ __forceinline__ float softplusf_fast(float x) {
    return fmaxf(x, 0.0f) + __logf(1.0f + __expf(-fabsf(x)));
}
__device__ __forceinline__ float sigmoidf_fast(float x) {
    return 1.0f / (1.0f + __expf(-x));
}
__device__ __forceinline__ float2 ffma2(float2 a, float2 b, float2 c) {
    unsigned long long ra = *reinterpret_cast<unsigned long long*>(&a);
    unsigned long long rb = *reinterpret_cast<unsigned long long*>(&b);
    unsigned long long rc = *reinterpret_cast<unsigned long long*>(&c);
    unsigned long long rd;
    asm("fma.rn.f32x2 %0, %1, %2, %3;" : "=l"(rd) : "l"(ra), "l"(rb), "l"(rc));
    return *reinterpret_cast<float2*>(&rd);
}

// ---------------------------------------------------------------------------
// Pack decode weights + precompute bg z-partial. 256 threads.
// ---------------------------------------------------------------------------
__global__ void pack_weights_kernel(const float* __restrict__ w1,
                                    const float* __restrict__ b1,
                                    const float* __restrict__ w2,
                                    const float* __restrict__ b2,
                                    const float* __restrict__ zbg,
                                    const float* __restrict__ bw1,
                                    const float* __restrict__ bb1) {
    const int tid = threadIdx.x;
    float2* wp2 = (float2*)g_wpack;
    float*  wpf = (float*)g_wpack;
    for (int i = tid; i < 1024; i += 256) {
        const int k = i >> 5, ch = i & 31;
        wp2[i] = make_float2(w2[(2 * k) * 33 + 1 + ch], w2[(2 * k + 1) * 33 + 1 + ch]);
    }
    if (tid < 32) {
        wp2[1024 + tid] = make_float2(w2[(2 * tid) * 33], w2[(2 * tid + 1) * 33]);
        wp2[1056 + tid] = ((const float2*)b1)[tid];
        wpf[2176 + tid] = b2[1 + tid];
    }
    if (tid == 0) wpf[2208] = b2[0];
    // w1 pre-scaled by 1/3 (feature mean folded into weights)
    {
        const float4* w1v4 = (const float4*)w1;
        const float sc = 1.0f / 3.0f;
        for (int i = tid; i < 512; i += 256) {
            float4 v = w1v4[i];
            v.x *= sc; v.y *= sc; v.z *= sc; v.w *= sc;
            g_wpack[560 + i] = v;
        }
    }
    // bg z-partial: tid = b*64 + u
    {
        const int b = tid >> 6, u = tid & 63;
        float acc = bb1[u];
        #pragma unroll 4
        for (int i = 0; i < 64; i++)
            acc = fmaf(zbg[b * 64 + i], bw1[(3 + i) * 64 + u], acc);
        g_bgz[b][u] = acc;
    }
}

// ---------------------------------------------------------------------------
// Transpose (B,3,C,256,256) -> bordered (B,3,258,258,C)
// ---------------------------------------------------------------------------
__global__ void transpose_planes_kernel(const float* __restrict__ planes) {
    __shared__ float tile[32][33];
    const int bp  = blockIdx.y;
    const int hw0 = blockIdx.x * 32;
    const float* src = planes + (size_t)bp * NCH * HRES * HRES;
    #pragma unroll
    for (int c = threadIdx.y; c < 32; c += 8)
        tile[c][threadIdx.x] = src[(size_t)c * (HRES * HRES) + hw0 + threadIdx.x];
    __syncthreads();
    float* dst = g_planesT + (size_t)bp * PLSZ;
    #pragma unroll
    for (int r = threadIdx.y; r < 32; r += 8) {
        const int hw = hw0 + r;
        const int y = hw >> 8, x = hw & 255;
        dst[(size_t)((y + 1) * HPAD + (x + 1)) * NCH + threadIdx.x] = tile[threadIdx.x][r];
    }
}

// ---------------------------------------------------------------------------
// Decode: sample-parallel warp-GEMM. 1 warp = 8 samples of one ray.
// ---------------------------------------------------------------------------
__global__ __launch_bounds__(128, 6) void decode_kernel(
    const float* __restrict__ ro, const float* __restrict__ rd, const int fine)
{
    __shared__ __align__(16) float2 sw1p[32 * 32];
    __shared__ __align__(16) float2 sw2p[32 * 32];
    __shared__ __align__(16) float2 wsig2[32];
    __shared__ __align__(16) float2 sb1p[32];
    __shared__ float  sb2r[32];
    __shared__ float  sb2sig;
    __shared__ __align__(16) float sstage[4][1152];

    const int tid  = threadIdx.x;
    const int warp = tid >> 5;
    const int lane = tid & 31;

    {   // stage weights: contiguous float4 copies from g_wpack
        float4* d1 = (float4*)sw1p;
        #pragma unroll
        for (int i = tid; i < 512; i += 128) d1[i] = g_wpack[560 + i];
        float4* d2 = (float4*)sw2p;
        #pragma unroll
        for (int i = tid; i < 512; i += 128) d2[i] = g_wpack[i];
        if (tid < 16) {
            ((float4*)wsig2)[tid] = g_wpack[512 + tid];
            ((float4*)sb1p)[tid]  = g_wpack[528 + tid];
        }
        const float* wpf = (const float*)g_wpack;
        if (tid < 32) sb2r[tid] = wpf[2176 + tid];
        if (tid == 0) sb2sig = wpf[2208];
    }
    __syncthreads();

    const int gw    = blockIdx.x * 4 + warp;
    const int ray   = gw / 6;
    const int sbase = (gw % 6) * 8;
    const int b     = ray >> 12;
    const int soff  = fine ? SC : 0;

    const float ox = __ldg(ro + ray * 3 + 0);
    const float oy = __ldg(ro + ray * 3 + 1);
    const float oz = __ldg(ro + ray * 3 + 2);
    const float dx = __ldg(rd + ray * 3 + 0);
    const float dy = __ldg(rd + ray * 3 + 1);
    const float dz = __ldg(rd + ray * 3 + 2);

    // premultiplied pixel-space ray constants: x_px = t*a + b
    const float axc = 256.0f * dx, bxc = fmaf(256.0f, ox, 127.5f);
    const float ayc = 256.0f * dy, byc = fmaf(256.0f, oy, 127.5f);
    const float azc = 256.0f * dz, bzc = fmaf(256.0f, oz, 127.5f);

    float* stg = sstage[warp];

    // --- gather 8 samples in 2 sub-passes of 4; lane=(s4, channel-group) ---
    {
        const int s4 = lane >> 3;       // sample within sub-pass (0..3)
        const int cg = lane & 7;        // channel group (4 channels)
        const float4* pb4 = (const float4*)g_planesT
                          + (size_t)(b * 3) * (PLSZ / 4) + (HPAD + 1) * 8 + cg;
        #pragma unroll
        for (int u = 0; u < 2; u++) {
            const int s = u * 4 + s4;
            float t;
            if (fine) t = __ldg(&g_zfine[(size_t)ray * NI + sbase + s]);
            else      t = 2.25f + ((float)(sbase + s) + 0.5f) * STEPF;
            const float X = fmaf(t, axc, bxc);
            const float Y = fmaf(t, ayc, byc);
            const float Z = fmaf(t, azc, bzc);
            float2 fxy = make_float2(0.0f, 0.0f);
            float2 fzw = make_float2(0.0f, 0.0f);
            #pragma unroll
            for (int p = 0; p < 3; p++) {
                const float x = (p == 2) ? Z : X;
                const float y = (p == 0) ? Y : ((p == 1) ? Z : X);
                const float x0f = floorf(x), y0f = floorf(y);
                const float wx = x - x0f, wy = y - y0f;
                const int x0 = (int)x0f, y0 = (int)y0f;
                const int x0c = min(max(x0,     -1), 256);
                const int x1c = min(max(x0 + 1, -1), 256);
                const int y0c = min(max(y0,     -1), 256);
                const int y1c = min(max(y0 + 1, -1), 256);
                const float4* base = pb4 + (size_t)p * (HPAD * HPAD * 8);
                const int r0 = y0c * HPAD, r1 = y1c * HPAD;
                const float4 v00 = __ldg(base + (r0 + x0c) * 8);
                const float4 v10 = __ldg(base + (r0 + x1c) * 8);
                const float4 v01 = __ldg(base + (r1 + x0c) * 8);
                const float4 v11 = __ldg(base + (r1 + x1c) * 8);
                const float iwx = 1.0f - wx, iwy = 1.0f - wy;
                const float w00 = iwx * iwy, w10 = wx * iwy;
                const float w01 = iwx * wy,  w11 = wx * wy;
                const float2 w00p = make_float2(w00, w00);
                const float2 w10p = make_float2(w10, w10);
                const float2 w01p = make_float2(w01, w01);
                const float2 w11p = make_float2(w11, w11);
                fxy = ffma2(make_float2(v00.x, v00.y), w00p, fxy);
                fxy = ffma2(make_float2(v10.x, v10.y), w10p, fxy);
                fxy = ffma2(make_float2(v01.x, v01.y), w01p, fxy);
                fxy = ffma2(make_float2(v11.x, v11.y), w11p, fxy);
                fzw = ffma2(make_float2(v00.z, v00.w), w00p, fzw);
                fzw = ffma2(make_float2(v10.z, v10.w), w10p, fzw);
                fzw = ffma2(make_float2(v01.z, v01.w), w01p, fzw);
                fzw = ffma2(make_float2(v11.z, v11.w), w11p, fzw);
            }
            // raw sums staged; 1/3 mean folded into w1
            stg[(4 * cg + 0) * 12 + s] = fxy.x;
            stg[(4 * cg + 1) * 12 + s] = fxy.y;
            stg[(4 * cg + 2) * 12 + s] = fzw.x;
            stg[(4 * cg + 3) * 12 + s] = fzw.y;
        }
    }
    __syncwarp();

    // --- hidden layer: lane owns units (2*lane, 2*lane+1), 8 samples ---
    float2 acc[8];
    {
        const float2 bp = sb1p[lane];
        #pragma unroll
        for (int s = 0; s < 8; s++) acc[s] = bp;
    }
    #pragma unroll 8
    for (int c = 0; c < 32; c++) {
        const float4 f03 = *(const float4*)(stg + c * 12);
        const float4 f47 = *(const float4*)(stg + c * 12 + 4);
        const float2 w = sw1p[c * 32 + lane];
        acc[0] = ffma2(make_float2(f03.x, f03.x), w, acc[0]);
        acc[1] = ffma2(make_float2(f03.y, f03.y), w, acc[1]);
        acc[2] = ffma2(make_float2(f03.z, f03.z), w, acc[2]);
        acc[3] = ffma2(make_float2(f03.w, f03.w), w, acc[3]);
        acc[4] = ffma2(make_float2(f47.x, f47.x), w, acc[4]);
        acc[5] = ffma2(make_float2(f47.y, f47.y), w, acc[5]);
        acc[6] = ffma2(make_float2(f47.z, f47.z), w, acc[6]);
        acc[7] = ffma2(make_float2(f47.w, f47.w), w, acc[7]);
    }
    float h0[8], h1[8];
    #pragma unroll
    for (int s = 0; s < 8; s++) {
        h0[s] = softplusf_fast(acc[s].x);
        h1[s] = softplusf_fast(acc[s].y);
    }

    // --- sigma: partials + lane-exchange tree reduction ---
    {
        float p[8];
        const float2 ws = wsig2[lane];
        #pragma unroll
        for (int s = 0; s < 8; s++) p[s] = fmaf(h0[s], ws.x, h1[s] * ws.y);

        #pragma unroll
        for (int i = 0; i < 4; i++) {
            const float send = (lane & 16) ? p[i] : p[i + 4];
            const float recv = __shfl_xor_sync(0xffffffffu, send, 16);
            p[i] = ((lane & 16) ? p[i + 4] : p[i]) + recv;
        }
        #pragma unroll
        for (int i = 0; i < 2; i++) {
            const float send = (lane & 8) ? p[i] : p[i + 2];
            const float recv = __shfl_xor_sync(0xffffffffu, send, 8);
            p[i] = ((lane & 8) ? p[i + 2] : p[i]) + recv;
        }
        {
            const float send = (lane & 4) ? p[0] : p[1];
            const float recv = __shfl_xor_sync(0xffffffffu, send, 4);
            p[0] = ((lane & 4) ? p[1] : p[0]) + recv;
        }
        p[0] += __shfl_xor_sync(0xffffffffu, p[0], 2);
        p[0] += __shfl_xor_sync(0xffffffffu, p[0], 1);
        if ((lane & 3) == 0)
            g_sigma[(size_t)ray * NALL + soff + sbase + (lane >> 2)] = p[0] + sb2sig;
    }

    __syncwarp();
    *(float4*)(stg + lane * 36 + 0)  = make_float4(h0[0], h1[0], h0[1], h1[1]);
    *(float4*)(stg + lane * 36 + 4)  = make_float4(h0[2], h1[2], h0[3], h1[3]);
    *(float4*)(stg + lane * 36 + 8)  = make_float4(h0[4], h1[4], h0[5], h1[5]);
    *(float4*)(stg + lane * 36 + 12) = make_float4(h0[6], h1[6], h0[7], h1[7]);
    __syncwarp();

    // --- output layer (only o2[8] live) ---
    float2 o2[8];
    #pragma unroll
    for (int s = 0; s < 8; s++) o2[s] = make_float2(0.0f, 0.0f);
    #pragma unroll 8
    for (int k = 0; k < 32; k++) {
        const float2 w = sw2p[k * 32 + lane];
        const float4 q0 = *(const float4*)(stg + k * 36 + 0);
        const float4 q1 = *(const float4*)(stg + k * 36 + 4);
        const float4 q2 = *(const float4*)(stg + k * 36 + 8);
        const float4 q3 = *(const float4*)(stg + k * 36 + 12);
        o2[0] = ffma2(make_float2(q0.x, q0.y), w, o2[0]);
        o2[1] = ffma2(make_float2(q0.z, q0.w), w, o2[1]);
        o2[2] = ffma2(make_float2(q1.x, q1.y), w, o2[2]);
        o2[3] = ffma2(make_float2(q1.z, q1.w), w, o2[3]);
        o2[4] = ffma2(make_float2(q2.x, q2.y), w, o2[4]);
        o2[5] = ffma2(make_float2(q2.z, q2.w), w, o2[5]);
        o2[6] = ffma2(make_float2(q3.x, q3.y), w, o2[6]);
        o2[7] = ffma2(make_float2(q3.z, q3.w), w, o2[7]);
    }

    const float bb = sb2r[lane];
    __half* grow = g_rgbh + ((size_t)ray * NALL + soff + sbase) * NCH + lane;
    #pragma unroll
    for (int s = 0; s < 8; s++)
        grow[s * NCH] = __float2half(sigmoidf_fast(o2[s].x + o2[s].y + bb) * 1.002f - 0.001f);
}

// ---------------------------------------------------------------------------
// March: warp-parallel predicated scans.
// ---------------------------------------------------------------------------
__global__ __launch_bounds__(128) void march_kernel() {
    __shared__ float salpha[4][47];
    __shared__ float swcl[4][47];
    __shared__ float swk[4][45];
    __shared__ float scdf[4][46];

    const int warp = threadIdx.x >> 5;
    const int lane = threadIdx.x & 31;
    const int ray  = blockIdx.x * 4 + warp;

    const float* sg = g_sigma + (size_t)ray * NALL;
    for (int i = lane; i < 47; i += 32) {
        const float dens = softplusf_fast(0.5f * (__ldg(sg + i) + __ldg(sg + i + 1)) - 1.0f);
        salpha[warp][i] = 1.0f - __expf(-dens * STEPF);
    }
    __syncwarp();

    {
        float Ta = 1.0f, Tb = 1.0f;
        #pragma unroll 4
        for (int j = 0; j < 46; j++) {
            const float fj = 1.0f - salpha[warp][j] + 1e-10f;
            if (j < lane)      Ta *= fj;
            if (j < lane + 32) Tb *= fj;
        }
        swcl[warp][lane] = salpha[warp][lane] * Ta;
        if (lane + 32 < 47)
            swcl[warp][lane + 32] = salpha[warp][lane + 32] * Tb;
    }
    __syncwarp();

    float ssum = 0.0f;
    #pragma unroll
    for (int kk = 0; kk < 2; kk++) {
        const int k = lane + kk * 32;
        if (k < 45) {
            const float a  = fmaxf(swcl[warp][k],     swcl[warp][k + 1]) + 0.01f;
            const float bb = fmaxf(swcl[warp][k + 1], swcl[warp][k + 2]) + 0.01f;
            const float v  = 0.5f * (a + bb) + 0.01f + 1e-5f;
            swk[warp][k] = v;
            ssum += v;
        }
    }
    #pragma unroll
    for (int off = 16; off; off >>= 1)
        ssum += __shfl_xor_sync(0xffffffffu, ssum, off);
    const float inv = 1.0f / ssum;
    __syncwarp();

    {
        float ca = 0.0f, cb = 0.0f;
        #pragma unroll 4
        for (int j = 0; j < 45; j++) {
            const float vj = swk[warp][j];
            if (j <= lane)      ca += vj;
            if (j <= lane + 32) cb += vj;
        }
        if (lane == 0) scdf[warp][0] = 0.0f;
        scdf[warp][lane + 1] = ca * inv;
        if (lane + 33 <= 45) scdf[warp][lane + 33] = cb * inv;
    }
    __syncwarp();

    for (int i = lane; i < NI; i += 32) {
        const float u = ((float)i + 0.5f) * (1.0f / 48.0f);
        int idx = 0;
        while (idx < 46 && scdf[warp][idx] <= u) idx++;
        int below = idx - 1; if (below < 0) below = 0; if (below > 45) below = 45;
        int above = idx;     if (above > 45) above = 45;
        const float cb = scdf[warp][below], ca = scdf[warp][above];
        float den = ca - cb; if (den < 1e-5f) den = 1.0f;
        const float bbv = 2.25f + ((float)below + 1.0f) * STEPF;
        const float bav = 2.25f + ((float)above + 1.0f) * STEPF;
        g_zfine[(size_t)ray * NI + i] = fmaf((u - cb) / den, bav - bbv, bbv);
    }
}

// ---------------------------------------------------------------------------
// Final: merge + parallel-scan march + cheap bg MLP + composite. 1 warp/ray.
// ---------------------------------------------------------------------------
__global__ __launch_bounds__(128) void final_kernel(
    const float* __restrict__ rd,
    const float* __restrict__ bw1, const float* __restrict__ bw2,
    const float* __restrict__ bb2, float* __restrict__ out)
{
    __shared__ float zall[4][NALL];
    __shared__ float sig[4][NALL];
    __shared__ unsigned char perm[4][NALL];
    __shared__ float alpha_s[4][NALL - 1];
    __shared__ float wall[4][NALL - 1];
    __shared__ float bgh[4][64];
    __shared__ __align__(16) float sbw2[64 * 32];

    const int tid  = threadIdx.x;
    const int warp = tid >> 5;
    const int lane = tid & 31;
    const int ray  = blockIdx.x * 4 + warp;
    const int b    = ray >> 12;

    // stage bw2 (8KB) once per block
    {
        const float4* src = (const float4*)bw2;
        float4* dst = (float4*)sbw2;
        #pragma unroll
        for (int i = tid; i < 512; i += 128) dst[i] = src[i];
    }

    const float dx = __ldg(rd + ray * 3 + 0);
    const float dy = __ldg(rd + ray * 3 + 1);
    const float dz = __ldg(rd + ray * 3 + 2);

    for (int i = lane; i < NALL; i += 32) {
        sig[warp][i] = __ldg(&g_sigma[(size_t)ray * NALL + i]);
        zall[warp][i] = (i < SC) ? (2.25f + ((float)i + 0.5f) * STEPF)
                                 : __ldg(&g_zfine[(size_t)ray * NI + i - SC]);
    }

    // --- bg layer 1: z-part precomputed (g_bgz), only 3 direction FMAs ---
    {
        float a0 = g_bgz[b][lane];
        float a1 = g_bgz[b][lane + 32];
        a0 = fmaf(dx, __ldg(bw1 + 0 * 64 + lane), a0);
        a1 = fmaf(dx, __ldg(bw1 + 0 * 64 + 32 + lane), a1);
        a0 = fmaf(dy, __ldg(bw1 + 1 * 64 + lane), a0);
        a1 = fmaf(dy, __ldg(bw1 + 1 * 64 + 32 + lane), a1);
        a0 = fmaf(dz, __ldg(bw1 + 2 * 64 + lane), a0);
        a1 = fmaf(dz, __ldg(bw1 + 2 * 64 + 32 + lane), a1);
        bgh[warp][lane]      = softplusf_fast(a0);
        bgh[warp][lane + 32] = softplusf_fast(a1);
    }
    __syncthreads();   // bw2 staged + bgh ready

    float bgc_r = __ldg(bb2 + lane);
    #pragma unroll 8
    for (int h = 0; h < 64; h++)
        bgc_r = fmaf(bgh[warp][h], sbw2[h * 32 + lane], bgc_r);
    bgc_r = sigmoidf_fast(bgc_r);
    __syncwarp();

    // --- stable merge by rank-counting ---
    for (int i = lane; i < SC; i += 32) {
        const float zv = zall[warp][i];
        int c = 0;
        #pragma unroll 8
        for (int k = 0; k < NI; k++) c += (zall[warp][SC + k] < zv) ? 1 : 0;
        perm[warp][i + c] = (unsigned char)i;
    }
    for (int j = lane; j < NI; j += 32) {
        const float zv = zall[warp][SC + j];
        int c = 0;
        #pragma unroll 8
        for (int k = 0; k < SC; k++) c += (zall[warp][k] <= zv) ? 1 : 0;
        perm[warp][j + c] = (unsigned char)(SC + j);
    }
    __syncwarp();

    for (int k = lane; k < NALL - 1; k += 32) {
        const float delta = zall[warp][perm[warp][k + 1]] - zall[warp][perm[warp][k]];
        const float dens  = softplusf_fast(0.5f * (sig[warp][perm[warp][k]] +
                                                   sig[warp][perm[warp][k + 1]]) - 1.0f);
        alpha_s[warp][k] = 1.0f - __expf(-dens * delta);
    }
    __syncwarp();

    // --- transmittance: predicated product scan over 95 factors ---
    float T0 = 1.0f, T1 = 1.0f, T2 = 1.0f, Tall = 1.0f;
    #pragma unroll 4
    for (int j = 0; j < NALL - 1; j++) {
        const float fj = 1.0f - alpha_s[warp][j] + 1e-10f;
        if (j < lane)      T0 *= fj;
        if (j < lane + 32) T1 *= fj;
        if (j < lane + 64) T2 *= fj;
        Tall *= fj;
    }
    float wt = 0.0f, dacc = 0.0f;
    {
        const int k = lane;
        const float w = alpha_s[warp][k] * T0;
        wall[warp][k] = w;
        wt += w;
        dacc = fmaf(w, 0.5f * (zall[warp][perm[warp][k]] + zall[warp][perm[warp][k + 1]]), dacc);
    }
    {
        const int k = lane + 32;
        const float w = alpha_s[warp][k] * T1;
        wall[warp][k] = w;
        wt += w;
        dacc = fmaf(w, 0.5f * (zall[warp][perm[warp][k]] + zall[warp][perm[warp][k + 1]]), dacc);
    }
    if (lane + 64 < NALL - 1) {
        const int k = lane + 64;
        const float w = alpha_s[warp][k] * T2;
        wall[warp][k] = w;
        wt += w;
        dacc = fmaf(w, 0.5f * (zall[warp][perm[warp][k]] + zall[warp][perm[warp][k + 1]]), dacc);
    }
    #pragma unroll
    for (int off = 16; off; off >>= 1) {
        wt   += __shfl_xor_sync(0xffffffffu, wt, off);
        dacc += __shfl_xor_sync(0xffffffffu, dacc, off);
    }
    __syncwarp();

    // --- composite (lane = channel; half rgb stream) ---
    const size_t rbase = (size_t)ray * NALL * NCH + lane;
    float rprev = __half2float(__ldg(&g_rgbh[rbase + (size_t)perm[warp][0] * NCH]));
    float acc = 0.0f;
    #pragma unroll 5
    for (int k = 0; k < NALL - 1; k++) {
        const float rnext = __half2float(__ldg(&g_rgbh[rbase + (size_t)perm[warp][k + 1] * NCH]));
        acc = fmaf(wall[warp][k], 0.5f * (rprev + rnext), acc);
        rprev = rnext;
    }
    acc = fmaf(Tall, bgc_r, acc);

    float* out_rgb   = out;
    float* out_depth = out + (size_t)NR * 32;
    float* out_wsum  = out + (size_t)NR * 33;

    out_rgb[(size_t)ray * 32 + lane] = acc * 2.0f - 1.0f;
    if (lane == 0) {
        float dv = dacc / wt;
        if (dv != dv) dv = INFINITY;
        const float ZMIN = 2.25f + 0.5f  * STEPF;
        const float ZMAX = 2.25f + 47.5f * STEPF;
        dv = fminf(fmaxf(dv, ZMIN), ZMAX);
        out_depth[ray] = dv;
        out_wsum[ray]  = wt;
    }
}

// ---------------------------------------------------------------------------
extern "C" void kernel_launch(void* const* d_in, const int* in_sizes, int n_in,
                              void* d_out, int out_size) {
    const float* planes = (const float*)d_in[0];
    const float* ro     = (const float*)d_in[1];
    const float* rd     = (const float*)d_in[2];
    const float* zbg    = (const float*)d_in[3];
    const float* w1     = (const float*)d_in[4];
    const float* b1     = (const float*)d_in[5];
    const float* w2     = (const float*)d_in[6];
    const float* b2     = (const float*)d_in[7];
    const float* bw1    = (const float*)d_in[8];
    const float* bb1    = (const float*)d_in[9];
    const float* bw2    = (const float*)d_in[10];
    const float* bb2    = (const float*)d_in[11];
    float* out = (float*)d_out;

    pack_weights_kernel<<<1, 256>>>(w1, b1, w2, b2, zbg, bw1, bb1);
    dim3 tgrid(HRES * HRES / 32, BATCH * 3);
    transpose_planes_kernel<<<tgrid, dim3(32, 8)>>>(planes);

    const int decode_blocks = NR * 6 / 4;
    decode_kernel<<<decode_blocks, 128>>>(ro, rd, 0);
    march_kernel<<<NR / 4, 128>>>();
    decode_kernel<<<decode_blocks, 128>>>(ro, rd, 1);
    final_kernel<<<NR / 4, 128>>>(rd, bw1, bw2, bb2, out);
}